// round 12
// baseline (speedup 1.0000x reference)
#include <cuda_runtime.h>
#include <math.h>

#define NB 128
#define NT 256
#define NE 300
#define NH 512
#define NG 2048     // 4*NH
#define NC 11
#define TSTART 9
#define TSTOP 10
#define NEGV -100000.0f
#define MROWS (NB*NT)   // 32768
#define NBLK 64         // persistent grid size (fat blocks)

// ---------------- scratch (static device memory; no allocations) ----------------
__device__ float g_gxf[(size_t)MROWS * NG];       // forward-dir input projection
__device__ float g_gxr[(size_t)MROWS * NG];       // reverse-dir input projection
__device__ float g_out0[(size_t)MROWS * 2 * NH];  // layer0 output (concat fwd|bwd)
__device__ float g_out1[(size_t)MROWS * 2 * NH];  // layer1 output
__device__ unsigned g_htf[2 * 2 * NB * NH];       // ping-pong h, stored as tf32 bits
__device__ float g_emis[(size_t)MROWS * NC];
__device__ unsigned char g_bt[(size_t)MROWS * NC];
__device__ float g_lossb[NB];

// ---------------- two-level tree barrier, one per direction group ---------------
// 64 blocks: leaf = bid>>3 (8 arrivals each), 4 leaves per direction root.
// Monotonic counters; reset_bar re-zeroes per graph replay. ONLY thread 0 of each
// block ever touches these (R9/R11 lesson: no all-thread global polling).
__device__ unsigned g_leafc[8 * 32];     // 128B apart
__device__ unsigned g_rootc[2 * 32];
__device__ volatile unsigned g_genv[2 * 32];

__global__ void reset_bar()
{
    int i = threadIdx.x;
    if (i < 256) ((unsigned*)g_leafc)[i] = 0u;
    if (i < 64)  ((unsigned*)g_rootc)[i] = 0u;
    if (i < 64)  ((unsigned*)g_genv)[i]  = 0u;
}

__device__ __forceinline__ void bar_arrive(int grp, int leaf)
{
    __syncthreads();                       // all block stores issued
    if (threadIdx.x == 0) {
        __threadfence();                   // h stores visible device-wide
        unsigned p = atomicAdd(&g_leafc[leaf * 32], 1u);
        if ((p & 7u) == 7u) {
            unsigned q = atomicAdd(&g_rootc[grp * 32], 1u);
            if ((q & 3u) == 3u) {
                __threadfence();
                g_genv[grp * 32] = (q >> 2) + 1u;   // gen counter
            }
        }
    }
}

__device__ __forceinline__ void bar_wait(int grp, unsigned my)
{
    if (threadIdx.x == 0) {
        while (g_genv[grp * 32] <= my) { }
    }
    __syncthreads();
    // no post-wake fence: cross-block data (h) is read via cp.async.cg (L2-direct);
    // all L1-cached loads (gx, seq_len, weights) are immutable.
}

// ---------------- tf32 helpers --------------------------------------------------
__device__ __forceinline__ unsigned f2tf(float x)
{
    unsigned y;
    asm("cvt.rna.tf32.f32 %0, %1;" : "=r"(y) : "f"(x));
    return y;
}

__device__ __forceinline__ void mma_tf32(float* d, const unsigned* a, const unsigned* b)
{
    asm volatile(
        "mma.sync.aligned.m16n8k8.row.col.f32.tf32.tf32.f32 "
        "{%0,%1,%2,%3}, {%4,%5,%6,%7}, {%8,%9}, {%0,%1,%2,%3};\n"
        : "+f"(d[0]), "+f"(d[1]), "+f"(d[2]), "+f"(d[3])
        : "r"(a[0]), "r"(a[1]), "r"(a[2]), "r"(a[3]), "r"(b[0]), "r"(b[1]));
}

// ---------------- tf32 tensor-core gx GEMM (unchanged, proven) ------------------
#define GP 8
__global__ __launch_bounds__(256) void gx_gemm_tc(
    const float* __restrict__ emb, const int* __restrict__ tokens,
    const float* __restrict__ W0, const float* __restrict__ bi0, const float* __restrict__ bh0,
    const float* __restrict__ W1, const float* __restrict__ bi1, const float* __restrict__ bh1,
    int K, int gather)
{
    int dir = blockIdx.z;
    const float* W  = dir ? W1  : W0;
    const float* bi = dir ? bi1 : bi0;
    const float* bh = dir ? bh1 : bh0;
    float* out = dir ? g_gxr : g_gxf;

    __shared__ unsigned As[16][128 + GP];
    __shared__ unsigned Bs[16][128 + GP];

    int tid  = threadIdx.x;
    int warp = tid >> 5;
    int lane = tid & 31;
    int quad = lane >> 2;
    int l4   = lane & 3;
    int wm   = (warp >> 1) * 32;
    int wn   = (warp & 1) * 64;

    int m0 = blockIdx.y * 128;
    int n0 = blockIdx.x * 128;

    float acc[2][8][4];
#pragma unroll
    for (int i = 0; i < 2; i++)
#pragma unroll
        for (int j = 0; j < 8; j++)
#pragma unroll
            for (int q = 0; q < 4; q++) acc[i][j][q] = 0.f;

    int kiters = (K + 15) >> 4;
    for (int kt = 0; kt < kiters; kt++) {
        int k0 = kt << 4;
        bool full = (k0 + 16 <= K);

#pragma unroll
        for (int r = 0; r < 2; r++) {
            int f  = tid + 256 * r;
            int mm = f >> 2;
            int c4 = (f & 3) * 4;
            int row = m0 + mm;
            const float* src = gather ? (emb + (size_t)tokens[row] * NE)
                                      : (g_out0 + (size_t)row * (2 * NH));
            if (full) {
                float4 v = *(const float4*)(src + k0 + c4);
                As[c4 + 0][mm] = f2tf(v.x);
                As[c4 + 1][mm] = f2tf(v.y);
                As[c4 + 2][mm] = f2tf(v.z);
                As[c4 + 3][mm] = f2tf(v.w);
            } else {
#pragma unroll
                for (int j = 0; j < 4; j++) {
                    int k = k0 + c4 + j;
                    As[c4 + j][mm] = (k < K) ? f2tf(src[k]) : 0u;
                }
            }
        }
#pragma unroll
        for (int r = 0; r < 2; r++) {
            int f  = tid + 256 * r;
            int nn = f >> 2;
            int c4 = (f & 3) * 4;
            const float* src = W + (size_t)(n0 + nn) * K;
            if (full) {
                float4 v = *(const float4*)(src + k0 + c4);
                Bs[c4 + 0][nn] = f2tf(v.x);
                Bs[c4 + 1][nn] = f2tf(v.y);
                Bs[c4 + 2][nn] = f2tf(v.z);
                Bs[c4 + 3][nn] = f2tf(v.w);
            } else {
#pragma unroll
                for (int j = 0; j < 4; j++) {
                    int k = k0 + c4 + j;
                    Bs[c4 + j][nn] = (k < K) ? f2tf(src[k]) : 0u;
                }
            }
        }
        __syncthreads();

#pragma unroll
        for (int ks = 0; ks < 16; ks += 8) {
            unsigned a[2][4], b[8][2];
#pragma unroll
            for (int mt = 0; mt < 2; mt++) {
                int mb = wm + mt * 16;
                a[mt][0] = As[ks + l4][mb + quad];
                a[mt][1] = As[ks + l4][mb + quad + 8];
                a[mt][2] = As[ks + l4 + 4][mb + quad];
                a[mt][3] = As[ks + l4 + 4][mb + quad + 8];
            }
#pragma unroll
            for (int nt = 0; nt < 8; nt++) {
                int nb = wn + nt * 8;
                b[nt][0] = Bs[ks + l4][nb + quad];
                b[nt][1] = Bs[ks + l4 + 4][nb + quad];
            }
#pragma unroll
            for (int mt = 0; mt < 2; mt++)
#pragma unroll
                for (int nt = 0; nt < 8; nt++)
                    mma_tf32(acc[mt][nt], a[mt], b[nt]);
        }
        __syncthreads();
    }

#pragma unroll
    for (int mt = 0; mt < 2; mt++) {
        int r0 = m0 + wm + mt * 16 + quad;
#pragma unroll
        for (int nt = 0; nt < 8; nt++) {
            int col = n0 + wn + nt * 8 + l4 * 2;
            float bsum0 = bi[col] + bh[col];
            float bsum1 = bi[col + 1] + bh[col + 1];
            float2 v0 = make_float2(acc[mt][nt][0] + bsum0, acc[mt][nt][1] + bsum1);
            float2 v1 = make_float2(acc[mt][nt][2] + bsum0, acc[mt][nt][3] + bsum1);
            *(float2*)&out[(size_t)r0 * NG + col] = v0;
            *(float2*)&out[(size_t)(r0 + 8) * NG + col] = v1;
        }
    }
}

// ---------------- tensor-core persistent bidirectional LSTM (fat blocks) -------
// 64 blocks: dir = bid>>5, hc0 = (bid&31)*16 -> block owns 16 h-cols (64 gate
// cols). Halves per-step L2 h traffic (16MB vs 32MB) and barrier population.
#define WSS 72   // Ws row stride: conflict-free B-frag loads (8*l4+quad distinct)
#define HSS 68   // hs row stride (u32): conflict-free A-frags
#define WS_U (NH * WSS)       // 36864 u32 = 147456 B
#define HS_U (NB * HSS)       // 8704 u32 per buffer
#define LSTM_SMEM ((WS_U + 2 * HS_U) * 4)   // 217088 bytes

__device__ __forceinline__ void stage_chunk(const unsigned* __restrict__ hsrc,
                                            unsigned* __restrict__ dstbase,
                                            int k0c, int tid)
{
#pragma unroll
    for (int r = 0; r < 8; r++) {
        int f   = tid + 256 * r;       // 0..2047 uint4s
        int row = f >> 4;
        int kk4 = (f & 15) * 4;
        unsigned daddr = (unsigned)__cvta_generic_to_shared(dstbase + row * HSS + kk4);
        const unsigned* src = hsrc + row * NH + k0c + kk4;
        asm volatile("cp.async.cg.shared.global [%0], [%1], 16;" :: "r"(daddr), "l"(src));
    }
}

__global__ __launch_bounds__(256) void lstm_persist_tc(
    const int* __restrict__ seq_len,
    const float* __restrict__ Whf, const float* __restrict__ Whr,
    int layer)
{
    extern __shared__ unsigned usmem[];
    unsigned* Wsm = usmem;              // [512][72] tf32 Whh slice: Wsm[k][c], c=g*16+j
    unsigned* hs0 = usmem + WS_U;       // chunk buffer 0: [128][68]
    unsigned* hs1 = hs0 + HS_U;         // chunk buffer 1

    int tid  = threadIdx.x;
    int bid  = blockIdx.x;
    int dir  = bid >> 5;
    int hc0  = (bid & 31) * 16;
    int grp  = dir;                     // barrier group per direction
    int leaf = bid >> 3;                // 0..7, 4 per group

    int w    = tid >> 5;
    int lane = tid & 31;
    int quad = lane >> 2;
    int l4   = lane & 3;

    const float* W   = dir ? Whr : Whf;
    const float* gxp = dir ? g_gxr : g_gxf;
    float* outp = layer ? g_out1 : g_out0;

    unsigned gen = g_genv[grp * 32];    // stable at launch boundary

    // resident Whh slice -> tf32 smem: Wsm[k*WSS + c] = W[g*512+hc0+j][k], c=g*16+j
    for (int jj = tid; jj < 64 * NH; jj += 256) {
        int c = jj >> 9, k = jj & 511;
        int g = c >> 4, j = c & 15;
        Wsm[k * WSS + c] = f2tf(W[(size_t)(g * NH + hc0 + j) * NH + k]);
    }

    // zero h ping buffer 0 (each block zeroes a disjoint 2048-chunk)
#pragma unroll
    for (int i = 0; i < 8; i++)
        g_htf[bid * 2048 + i * 256 + tid] = 0u;

    int b0 = 16 * w + quad;
    int b1 = b0 + 8;
    int sl0 = seq_len[b0];
    int sl1 = seq_len[b1];
    float c_reg[8] = {0.f, 0.f, 0.f, 0.f, 0.f, 0.f, 0.f, 0.f};
    float h_reg[8] = {0.f, 0.f, 0.f, 0.f, 0.f, 0.f, 0.f, 0.f};

    // per-thread column bases: tile nt covers cols hc0 + nt*8 + 2*l4 + {0,1}
    int col0 = hc0 + 2 * l4;            // nt=0
    int col1 = hc0 + 8 + 2 * l4;        // nt=1

    // prefetch gx for step 0 (immutable; legal before the barrier)
    float gxv[4][8];
    {
        int t_data0 = dir ? (NT - 1) : 0;
        size_t r0 = (size_t)(b0 * NT + t_data0) * NG;
        size_t r1 = (size_t)(b1 * NT + t_data0) * NG;
#pragma unroll
        for (int g = 0; g < 4; g++) {
            float2 a0 = *(const float2*)&gxp[r0 + g * NH + col0];
            float2 a1 = *(const float2*)&gxp[r1 + g * NH + col0];
            float2 b0v = *(const float2*)&gxp[r0 + g * NH + col1];
            float2 b1v = *(const float2*)&gxp[r1 + g * NH + col1];
            gxv[g][0] = a0.x; gxv[g][1] = a0.y; gxv[g][2] = a1.x; gxv[g][3] = a1.y;
            gxv[g][4] = b0v.x; gxv[g][5] = b0v.y; gxv[g][6] = b1v.x; gxv[g][7] = b1v.y;
        }
    }

    bar_arrive(grp, leaf);              // h zero-init visible everywhere
    bar_wait(grp, gen); gen++;

    for (int t = 0; t < NT; t++) {
        int rb = t & 1;
        int wbuf = 1 - rb;
        int t_data = dir ? (NT - 1 - t) : t;

        const unsigned* hsrc = g_htf + rb * (2 * NB * NH) + dir * (NB * NH);

        // kick off h chunk 0 immediately after the barrier
        stage_chunk(hsrc, hs0, 0, tid);
        asm volatile("cp.async.commit_group;");

        float acc[4][2][4];
#pragma unroll
        for (int g = 0; g < 4; g++)
#pragma unroll
            for (int nt = 0; nt < 2; nt++)
#pragma unroll
                for (int q = 0; q < 4; q++) acc[g][nt][q] = 0.f;

#pragma unroll
        for (int chunk = 0; chunk < 8; chunk++) {
            unsigned* cur = (chunk & 1) ? hs1 : hs0;
            if (chunk < 7) {
                unsigned* nxt = (chunk & 1) ? hs0 : hs1;
                stage_chunk(hsrc, nxt, (chunk + 1) * 64, tid);
                asm volatile("cp.async.commit_group;");
                asm volatile("cp.async.wait_group 1;");
            } else {
                asm volatile("cp.async.wait_group 0;");
            }
            __syncthreads();

            int k0c = chunk * 64;
#pragma unroll
            for (int ks = 0; ks < 8; ks++) {
                int kk = ks * 8;
                int kg = k0c + kk;
                unsigned a[4];
                a[0] = cur[b0 * HSS + kk + l4];
                a[1] = cur[b1 * HSS + kk + l4];
                a[2] = cur[b0 * HSS + kk + l4 + 4];
                a[3] = cur[b1 * HSS + kk + l4 + 4];
#pragma unroll
                for (int g = 0; g < 4; g++) {
#pragma unroll
                    for (int nt = 0; nt < 2; nt++) {
                        unsigned b[2];
                        b[0] = Wsm[(kg + l4) * WSS + g * 16 + nt * 8 + quad];
                        b[1] = Wsm[(kg + l4 + 4) * WSS + g * 16 + nt * 8 + quad];
                        mma_tf32(acc[g][nt], a, b);
                    }
                }
            }
            __syncthreads();
        }

        // ---- Phase B: cell update; store ONLY h before arrival ----
        unsigned* hdst = g_htf + wbuf * (2 * NB * NH) + dir * (NB * NH);
        bool mt0 = t_data < sl0;
        bool mt1 = t_data < sl1;
        float hout[8];
#pragma unroll
        for (int nt = 0; nt < 2; nt++) {
#pragma unroll
            for (int q = 0; q < 4; q++) {
                int idx = nt * 4 + q;
                int r   = q >> 1;
                float gi = acc[0][nt][q] + gxv[0][idx];
                float gf = acc[1][nt][q] + gxv[1][idx];
                float gg = acc[2][nt][q] + gxv[2][idx];
                float go = acc[3][nt][q] + gxv[3][idx];

                float iv = 1.f / (1.f + expf(-gi));
                float fv = 1.f / (1.f + expf(-gf));
                float ov = 1.f / (1.f + expf(-go));
                float gv = tanhf(gg);

                float cn = fv * c_reg[idx] + iv * gv;
                float hn = ov * tanhf(cn);

                bool mt = r ? mt1 : mt0;
                if (mt) { c_reg[idx] = cn; h_reg[idx] = hn; }
                hout[idx] = mt ? hn : 0.f;

                int b  = r ? b1 : b0;
                int hh = (nt ? col1 : col0) + (q & 1);
                hdst[b * NH + hh] = f2tf(h_reg[idx]);
            }
        }

        bar_arrive(grp, leaf);          // fence drains only the h stores

        // ---- hidden in the poll window: outp stores + next-step gx prefetch ----
#pragma unroll
        for (int nt = 0; nt < 2; nt++) {
#pragma unroll
            for (int q = 0; q < 4; q++) {
                int idx = nt * 4 + q;
                int b  = (q >> 1) ? b1 : b0;
                int hh = (nt ? col1 : col0) + (q & 1);
                outp[(size_t)(b * NT + t_data) * (2 * NH) + dir * NH + hh] = hout[idx];
            }
        }
        if (t + 1 < NT) {
            int tn = dir ? (NT - 2 - t) : (t + 1);
            size_t r0 = (size_t)(b0 * NT + tn) * NG;
            size_t r1 = (size_t)(b1 * NT + tn) * NG;
#pragma unroll
            for (int g = 0; g < 4; g++) {
                float2 a0 = *(const float2*)&gxp[r0 + g * NH + col0];
                float2 a1 = *(const float2*)&gxp[r1 + g * NH + col0];
                float2 b0v = *(const float2*)&gxp[r0 + g * NH + col1];
                float2 b1v = *(const float2*)&gxp[r1 + g * NH + col1];
                gxv[g][0] = a0.x; gxv[g][1] = a0.y; gxv[g][2] = a1.x; gxv[g][3] = a1.y;
                gxv[g][4] = b0v.x; gxv[g][5] = b0v.y; gxv[g][6] = b1v.x; gxv[g][7] = b1v.y;
            }
        }

        bar_wait(grp, gen); gen++;
    }
}

// ---------------- emission FC ---------------------------------------------------
__global__ void emis_kernel(const float* __restrict__ fw, const float* __restrict__ fb)
{
    int gtid = blockIdx.x * blockDim.x + threadIdx.x;
    int w = gtid >> 5;
    int lane = threadIdx.x & 31;
    if (w >= MROWS) return;
    const float* x = g_out1 + (size_t)w * (2 * NH);
    float acc[NC];
#pragma unroll
    for (int c = 0; c < NC; c++) acc[c] = 0.f;
    for (int k = lane; k < 2 * NH; k += 32) {
        float xv = x[k];
#pragma unroll
        for (int c = 0; c < NC; c++) acc[c] += xv * fw[c * 2 * NH + k];
    }
#pragma unroll
    for (int off = 16; off > 0; off >>= 1)
#pragma unroll
        for (int c = 0; c < NC; c++) acc[c] += __shfl_down_sync(0xffffffffu, acc[c], off);
    if (lane == 0) {
#pragma unroll
        for (int c = 0; c < NC; c++) g_emis[(size_t)w * NC + c] = acc[c] + fb[c];
    }
}

// ---------------- CRF -----------------------------------------------------------
__global__ void crf_kernel(const int* __restrict__ seq_len, const int* __restrict__ tags,
                           const float* __restrict__ trans, float* __restrict__ out)
{
    int b = blockIdx.x;
    int lane = threadIdx.x;
    __shared__ float tr[NC][NC + 1];
    __shared__ float vs[NC + 1], fs[NC + 1], vf[NC + 1], ff[NC + 1];

    for (int i = lane; i < NC * NC; i += 32) tr[i / NC][i % NC] = trans[i];
    if (lane < NC) { vs[lane] = 0.f; fs[lane] = NEGV; }
    __syncwarp();

    int sl = seq_len[b];
    for (int t = 0; t < NT; t++) {
        float vnew = 0.f, fnew = 0.f;
        if (lane < NC) {
            float emi = g_emis[(size_t)(b * NT + t) * NC + lane];
            float best = vs[0] + tr[0][lane]; int bi = 0;
            float m = fs[0] + tr[0][lane];
#pragma unroll
            for (int i = 1; i < NC; i++) {
                float v = vs[i] + tr[i][lane];
                if (v > best) { best = v; bi = i; }
                float fv = fs[i] + tr[i][lane];
                if (fv > m) m = fv;
            }
            float s = 0.f;
#pragma unroll
            for (int i = 0; i < NC; i++) s += expf(fs[i] + tr[i][lane] - m);
            vnew = best + emi;
            fnew = emi + m + logf(s);
            g_bt[(size_t)(b * NT + t) * NC + lane] = (unsigned char)bi;
        }
        __syncwarp();
        if (lane < NC && t < sl) { vs[lane] = vnew; fs[lane] = fnew; }
        __syncwarp();
    }
    if (lane < NC) {
        vf[lane] = vs[lane] + tr[lane][TSTOP];
        ff[lane] = fs[lane] + tr[lane][TSTOP];
    }
    __syncwarp();
    if (lane == 0) {
        int best = 0; float bv = vf[0];
        for (int j = 1; j < NC; j++) if (vf[j] > bv) { bv = vf[j]; best = j; }
        float m = ff[0];
        for (int j = 1; j < NC; j++) if (ff[j] > m) m = ff[j];
        float s = 0.f;
        for (int j = 0; j < NC; j++) s += expf(ff[j] - m);
        float fwd = m + logf(s);

        float gold = 0.f; int prev = TSTART;
        for (int t = 0; t < sl; t++) {
            int tg = tags[b * NT + t];
            gold += g_emis[(size_t)(b * NT + t) * NC + tg] + tr[prev][tg];
            prev = tg;
        }
        gold += tr[prev][TSTOP];
        g_lossb[b] = fwd - gold;

        int cur = best;
        for (int l = NT - 1; l >= 0; l--) {
            out[b * NT + l] = (l < sl) ? (float)cur : 0.f;
            if (l >= 1 && l <= sl - 1) cur = g_bt[(size_t)(b * NT + l) * NC + cur];
        }
    }
}

__global__ void loss_reduce(float* __restrict__ out)
{
    __shared__ float s[NB];
    int i = threadIdx.x;
    s[i] = g_lossb[i];
    __syncthreads();
    for (int off = NB / 2; off > 0; off >>= 1) {
        if (i < off) s[i] += s[i + off];
        __syncthreads();
    }
    if (i == 0) out[MROWS] = s[0] / (float)NB;
}

// ---------------- launcher ------------------------------------------------------
extern "C" void kernel_launch(void* const* d_in, const int* in_sizes, int n_in,
                              void* d_out, int out_size)
{
    const int*   tokens   = (const int*)d_in[0];
    const int*   seq_len  = (const int*)d_in[1];
    const int*   tags     = (const int*)d_in[3];
    const float* emb      = (const float*)d_in[4];
    const float* w_ih_l0  = (const float*)d_in[5];
    const float* w_hh_l0  = (const float*)d_in[6];
    const float* b_ih_l0  = (const float*)d_in[7];
    const float* b_hh_l0  = (const float*)d_in[8];
    const float* w_ih_l0r = (const float*)d_in[9];
    const float* w_hh_l0r = (const float*)d_in[10];
    const float* b_ih_l0r = (const float*)d_in[11];
    const float* b_hh_l0r = (const float*)d_in[12];
    const float* w_ih_l1  = (const float*)d_in[13];
    const float* w_hh_l1  = (const float*)d_in[14];
    const float* b_ih_l1  = (const float*)d_in[15];
    const float* b_hh_l1  = (const float*)d_in[16];
    const float* w_ih_l1r = (const float*)d_in[17];
    const float* w_hh_l1r = (const float*)d_in[18];
    const float* b_ih_l1r = (const float*)d_in[19];
    const float* b_hh_l1r = (const float*)d_in[20];
    const float* fc_w     = (const float*)d_in[21];
    const float* fc_b     = (const float*)d_in[22];
    const float* trans    = (const float*)d_in[23];
    float* out = (float*)d_out;

    static int smem_set = 0;
    if (!smem_set) {
        cudaFuncSetAttribute(lstm_persist_tc,
                             cudaFuncAttributeMaxDynamicSharedMemorySize, LSTM_SMEM);
        smem_set = 1;
    }

    dim3 ggx(NG / 128, MROWS / 128, 2);

    reset_bar<<<1, 256>>>();

    // ---- layer 0 ----
    gx_gemm_tc<<<ggx, 256>>>(emb, tokens,
                             w_ih_l0, b_ih_l0, b_hh_l0,
                             w_ih_l0r, b_ih_l0r, b_hh_l0r, NE, 1);
    lstm_persist_tc<<<NBLK, 256, LSTM_SMEM>>>(seq_len, w_hh_l0, w_hh_l0r, 0);

    // ---- layer 1 ----
    gx_gemm_tc<<<ggx, 256>>>(emb, tokens,
                             w_ih_l1, b_ih_l1, b_hh_l1,
                             w_ih_l1r, b_ih_l1r, b_hh_l1r, 2 * NH, 0);
    lstm_persist_tc<<<NBLK, 256, LSTM_SMEM>>>(seq_len, w_hh_l1, w_hh_l1r, 1);

    // ---- emissions + CRF ----
    emis_kernel<<<MROWS / 8, 256>>>(fc_w, fc_b);
    crf_kernel<<<NB, 32>>>(seq_len, tags, trans, out);
    loss_reduce<<<1, 128>>>(out);
}

// round 13
// speedup vs baseline: 1.5045x; 1.5045x over previous
#include <cuda_runtime.h>
#include <math.h>

#define NB 128
#define NT 256
#define NE 300
#define NH 512
#define NG 2048     // 4*NH
#define NC 11
#define TSTART 9
#define TSTOP 10
#define NEGV -100000.0f
#define MROWS (NB*NT)   // 32768
#define NBLK 128        // persistent grid size

// ---------------- scratch (static device memory; no allocations) ----------------
__device__ float g_gxf[(size_t)MROWS * NG];       // forward-dir input projection
__device__ float g_gxr[(size_t)MROWS * NG];       // reverse-dir input projection
__device__ float g_out0[(size_t)MROWS * 2 * NH];  // layer0 output (concat fwd|bwd)
__device__ float g_out1[(size_t)MROWS * 2 * NH];  // layer1 output
__device__ unsigned g_htf[2 * 2 * NB * NH];       // ping-pong h, stored as tf32 bits
__device__ float g_emis[(size_t)MROWS * NC];
__device__ unsigned char g_bt[(size_t)MROWS * NC];
__device__ float g_lossb[NB];

// ---------------- two-level tree barrier, one per direction group ---------------
// R10-proven: ONLY thread 0 of each block touches global sync state.
__device__ unsigned g_leafc[8 * 32];     // 128B apart
__device__ unsigned g_rootc[2 * 32];
__device__ volatile unsigned g_genv[2 * 32];

__global__ void reset_bar()
{
    int i = threadIdx.x;
    if (i < 256) ((unsigned*)g_leafc)[i] = 0u;
    if (i < 64)  ((unsigned*)g_rootc)[i] = 0u;
    if (i < 64)  ((unsigned*)g_genv)[i]  = 0u;
}

__device__ __forceinline__ void bar_arrive(int grp, int leaf)
{
    __syncthreads();                       // all block stores issued
    if (threadIdx.x == 0) {
        __threadfence();                   // h stores visible device-wide
        unsigned p = atomicAdd(&g_leafc[leaf * 32], 1u);
        if ((p & 15u) == 15u) {
            unsigned q = atomicAdd(&g_rootc[grp * 32], 1u);
            if ((q & 3u) == 3u) {
                __threadfence();
                g_genv[grp * 32] = (q >> 2) + 1u;   // gen counter
            }
        }
    }
}

__device__ __forceinline__ void bar_wait(int grp, unsigned my)
{
    if (threadIdx.x == 0) {
        while (g_genv[grp * 32] <= my) { }
    }
    __syncthreads();
    // no post-wake fence: cross-block data (h) is read via cp.async.cg (L2-direct);
    // all L1-cached loads (gx, seq_len, weights) are immutable.
}

// ---------------- tf32 helpers --------------------------------------------------
__device__ __forceinline__ unsigned f2tf(float x)
{
    unsigned y;
    asm("cvt.rna.tf32.f32 %0, %1;" : "=r"(y) : "f"(x));
    return y;
}

__device__ __forceinline__ void mma_tf32(float* d, const unsigned* a, const unsigned* b)
{
    asm volatile(
        "mma.sync.aligned.m16n8k8.row.col.f32.tf32.tf32.f32 "
        "{%0,%1,%2,%3}, {%4,%5,%6,%7}, {%8,%9}, {%0,%1,%2,%3};\n"
        : "+f"(d[0]), "+f"(d[1]), "+f"(d[2]), "+f"(d[3])
        : "r"(a[0]), "r"(a[1]), "r"(a[2]), "r"(a[3]), "r"(b[0]), "r"(b[1]));
}

// ---------------- tf32 gx GEMM with cp.async double buffering -------------------
// Smem tiles stored [m][k] / [n][k], row stride 20 u32 (conflict-free for both
// cp.async 16B stores and mma fragment loads). Raw fp32 bits are fed to the tf32
// mma (HW truncation) -> no CVT in the mainloop. K tail via cp.async src-size
// zero-fill.
#define GXS 20   // row stride in u32
__global__ __launch_bounds__(256) void gx_gemm_tc(
    const float* __restrict__ emb, const int* __restrict__ tokens,
    const float* __restrict__ W0, const float* __restrict__ bi0, const float* __restrict__ bh0,
    const float* __restrict__ W1, const float* __restrict__ bi1, const float* __restrict__ bh1,
    int K, int gather)
{
    int dir = blockIdx.z;
    const float* W  = dir ? W1  : W0;
    const float* bi = dir ? bi1 : bi0;
    const float* bh = dir ? bh1 : bh0;
    float* out = dir ? g_gxr : g_gxf;

    __shared__ unsigned As[2][128 * GXS];
    __shared__ unsigned Bs[2][128 * GXS];

    int tid  = threadIdx.x;
    int warp = tid >> 5;
    int lane = tid & 31;
    int quad = lane >> 2;
    int l4   = lane & 3;
    int wm   = (warp >> 1) * 32;
    int wn   = (warp & 1) * 64;

    int m0 = blockIdx.y * 128;
    int n0 = blockIdx.x * 128;

    float acc[2][8][4];
#pragma unroll
    for (int i = 0; i < 2; i++)
#pragma unroll
        for (int j = 0; j < 8; j++)
#pragma unroll
            for (int q = 0; q < 4; q++) acc[i][j][q] = 0.f;

    int kiters = (K + 15) >> 4;

    // stage tile kt into buffer buf (4 cp.async 16B per thread + commit)
    auto do_stage = [&](int buf, int kt) {
        int k0 = kt << 4;
#pragma unroll
        for (int r = 0; r < 2; r++) {
            int f  = tid + 256 * r;
            int mm = f >> 2;
            int c4 = (f & 3) * 4;
            int k  = k0 + c4;
            int row = m0 + mm;
            const float* src = gather ? (emb + (size_t)tokens[row] * NE + k)
                                      : (g_out0 + (size_t)row * (2 * NH) + k);
            int nb = (K - k) * 4; nb = nb < 0 ? 0 : (nb > 16 ? 16 : nb);
            unsigned d = (unsigned)__cvta_generic_to_shared(&As[buf][mm * GXS + c4]);
            asm volatile("cp.async.cg.shared.global [%0], [%1], 16, %2;"
                         :: "r"(d), "l"(src), "r"(nb));
        }
#pragma unroll
        for (int r = 0; r < 2; r++) {
            int f  = tid + 256 * r;
            int nn = f >> 2;
            int c4 = (f & 3) * 4;
            int k  = k0 + c4;
            const float* src = W + (size_t)(n0 + nn) * K + k;
            int nb = (K - k) * 4; nb = nb < 0 ? 0 : (nb > 16 ? 16 : nb);
            unsigned d = (unsigned)__cvta_generic_to_shared(&Bs[buf][nn * GXS + c4]);
            asm volatile("cp.async.cg.shared.global [%0], [%1], 16, %2;"
                         :: "r"(d), "l"(src), "r"(nb));
        }
        asm volatile("cp.async.commit_group;");
    };

    do_stage(0, 0);

    for (int kt = 0; kt < kiters; kt++) {
        int buf = kt & 1;
        if (kt + 1 < kiters) {
            do_stage(buf ^ 1, kt + 1);
            asm volatile("cp.async.wait_group 1;");
        } else {
            asm volatile("cp.async.wait_group 0;");
        }
        __syncthreads();

        const unsigned* Ab = As[buf];
        const unsigned* Bb = Bs[buf];
#pragma unroll
        for (int ks = 0; ks < 16; ks += 8) {
            unsigned a[2][4], b[8][2];
#pragma unroll
            for (int mt = 0; mt < 2; mt++) {
                int mb = wm + mt * 16;
                a[mt][0] = Ab[(mb + quad) * GXS + ks + l4];
                a[mt][1] = Ab[(mb + quad + 8) * GXS + ks + l4];
                a[mt][2] = Ab[(mb + quad) * GXS + ks + l4 + 4];
                a[mt][3] = Ab[(mb + quad + 8) * GXS + ks + l4 + 4];
            }
#pragma unroll
            for (int nt = 0; nt < 8; nt++) {
                int nb = wn + nt * 8;
                b[nt][0] = Bb[(nb + quad) * GXS + ks + l4];
                b[nt][1] = Bb[(nb + quad) * GXS + ks + l4 + 4];
            }
#pragma unroll
            for (int mt = 0; mt < 2; mt++)
#pragma unroll
                for (int nt = 0; nt < 8; nt++)
                    mma_tf32(acc[mt][nt], a[mt], b[nt]);
        }
        __syncthreads();
    }

#pragma unroll
    for (int mt = 0; mt < 2; mt++) {
        int r0 = m0 + wm + mt * 16 + quad;
#pragma unroll
        for (int nt = 0; nt < 8; nt++) {
            int col = n0 + wn + nt * 8 + l4 * 2;
            float bsum0 = bi[col] + bh[col];
            float bsum1 = bi[col + 1] + bh[col + 1];
            float2 v0 = make_float2(acc[mt][nt][0] + bsum0, acc[mt][nt][1] + bsum1);
            float2 v1 = make_float2(acc[mt][nt][2] + bsum0, acc[mt][nt][3] + bsum1);
            *(float2*)&out[(size_t)r0 * NG + col] = v0;
            *(float2*)&out[(size_t)(r0 + 8) * NG + col] = v1;
        }
    }
}

// ---------------- tensor-core persistent bidirectional LSTM (R10, proven) ------
#define WSS 40   // Ws row stride: conflict-free B-frag loads
#define HSS 68   // hs row stride (u32): conflict-free A-frags
#define WS_U (NH * WSS)       // 20480 u32
#define HS_U (NB * HSS)       // 8704 u32 per buffer
#define LSTM_SMEM ((WS_U + 2 * HS_U) * 4)   // 151552 bytes

__device__ __forceinline__ void stage_chunk(const unsigned* __restrict__ hsrc,
                                            unsigned* __restrict__ dstbase,
                                            int k0c, int tid)
{
#pragma unroll
    for (int r = 0; r < 8; r++) {
        int f   = tid + 256 * r;       // 0..2047 uint4s
        int row = f >> 4;
        int kk4 = (f & 15) * 4;
        unsigned daddr = (unsigned)__cvta_generic_to_shared(dstbase + row * HSS + kk4);
        const unsigned* src = hsrc + row * NH + k0c + kk4;
        asm volatile("cp.async.cg.shared.global [%0], [%1], 16;" :: "r"(daddr), "l"(src));
    }
}

__global__ __launch_bounds__(256) void lstm_persist_tc(
    const int* __restrict__ seq_len,
    const float* __restrict__ Whf, const float* __restrict__ Whr,
    int layer)
{
    extern __shared__ unsigned usmem[];
    unsigned* Wsm = usmem;              // [512][40] tf32 Whh slice
    unsigned* hs0 = usmem + WS_U;       // chunk buffer 0: [128][68]
    unsigned* hs1 = hs0 + HS_U;         // chunk buffer 1

    int tid  = threadIdx.x;
    int bid  = blockIdx.x;
    int dir  = bid >> 6;
    int hc0  = (bid & 63) * 8;
    int grp  = dir;                     // barrier group per direction
    int leaf = bid >> 4;                // 0..7, 4 per group

    int w    = tid >> 5;
    int lane = tid & 31;
    int quad = lane >> 2;
    int l4   = lane & 3;

    const float* W   = dir ? Whr : Whf;
    const float* gxp = dir ? g_gxr : g_gxf;
    float* outp = layer ? g_out1 : g_out0;

    unsigned gen = g_genv[grp * 32];    // stable at launch boundary

    // resident Whh slice -> tf32 smem: Wsm[k*WSS + c] = W[g*512+hc0+j][k]
    for (int jj = tid; jj < 32 * NH; jj += 256) {
        int c = jj >> 9, k = jj & 511;
        int g = c >> 3, j = c & 7;
        Wsm[k * WSS + c] = f2tf(W[(size_t)(g * NH + hc0 + j) * NH + k]);
    }

    // zero h ping buffer 0 (each block zeroes a disjoint 1024-chunk)
#pragma unroll
    for (int i = 0; i < 4; i++)
        g_htf[bid * 1024 + i * 256 + tid] = 0u;

    int b0 = 16 * w + quad;
    int b1 = b0 + 8;
    int hhbase = hc0 + 2 * l4;
    int sl0 = seq_len[b0];
    int sl1 = seq_len[b1];
    float c_reg[4] = {0.f, 0.f, 0.f, 0.f};
    float h_reg[4] = {0.f, 0.f, 0.f, 0.f};

    // prefetch gx for step 0 (immutable; legal before the barrier)
    float gxv[4][4];
    {
        int t_data0 = dir ? (NT - 1) : 0;
        size_t base0 = (size_t)(b0 * NT + t_data0) * NG + hhbase;
        size_t base1 = (size_t)(b1 * NT + t_data0) * NG + hhbase;
#pragma unroll
        for (int g = 0; g < 4; g++) {
            float2 v0 = *(const float2*)&gxp[base0 + g * NH];
            float2 v1 = *(const float2*)&gxp[base1 + g * NH];
            gxv[g][0] = v0.x; gxv[g][1] = v0.y;
            gxv[g][2] = v1.x; gxv[g][3] = v1.y;
        }
    }

    bar_arrive(grp, leaf);              // h zero-init visible everywhere
    bar_wait(grp, gen); gen++;

    for (int t = 0; t < NT; t++) {
        int rb = t & 1;
        int wbuf = 1 - rb;
        int t_data = dir ? (NT - 1 - t) : t;

        const unsigned* hsrc = g_htf + rb * (2 * NB * NH) + dir * (NB * NH);

        // kick off h chunk 0 immediately after the barrier
        stage_chunk(hsrc, hs0, 0, tid);
        asm volatile("cp.async.commit_group;");

        float acc[4][4];
#pragma unroll
        for (int g = 0; g < 4; g++)
#pragma unroll
            for (int q = 0; q < 4; q++) acc[g][q] = 0.f;

#pragma unroll
        for (int chunk = 0; chunk < 8; chunk++) {
            unsigned* cur = (chunk & 1) ? hs1 : hs0;
            if (chunk < 7) {
                unsigned* nxt = (chunk & 1) ? hs0 : hs1;
                stage_chunk(hsrc, nxt, (chunk + 1) * 64, tid);
                asm volatile("cp.async.commit_group;");
                asm volatile("cp.async.wait_group 1;");
            } else {
                asm volatile("cp.async.wait_group 0;");
            }
            __syncthreads();

            int k0c = chunk * 64;
#pragma unroll
            for (int ks = 0; ks < 8; ks++) {
                int kk = ks * 8;
                int kg = k0c + kk;
                unsigned a[4];
                a[0] = cur[b0 * HSS + kk + l4];
                a[1] = cur[b1 * HSS + kk + l4];
                a[2] = cur[b0 * HSS + kk + l4 + 4];
                a[3] = cur[b1 * HSS + kk + l4 + 4];
#pragma unroll
                for (int g = 0; g < 4; g++) {
                    unsigned b[2];
                    b[0] = Wsm[(kg + l4) * WSS + g * 8 + quad];
                    b[1] = Wsm[(kg + l4 + 4) * WSS + g * 8 + quad];
                    mma_tf32(acc[g], a, b);
                }
            }
            __syncthreads();
        }

        // ---- Phase B: cell update; store ONLY h before arrival ----
        unsigned* hdst = g_htf + wbuf * (2 * NB * NH) + dir * (NB * NH);
        bool mt0 = t_data < sl0;
        bool mt1 = t_data < sl1;
        float hout[4];
#pragma unroll
        for (int k = 0; k < 4; k++) {
            int r  = k >> 1;
            float gi = acc[0][k] + gxv[0][k];
            float gf = acc[1][k] + gxv[1][k];
            float gg = acc[2][k] + gxv[2][k];
            float go = acc[3][k] + gxv[3][k];

            float iv = 1.f / (1.f + expf(-gi));
            float fv = 1.f / (1.f + expf(-gf));
            float ov = 1.f / (1.f + expf(-go));
            float gv = tanhf(gg);

            float cn = fv * c_reg[k] + iv * gv;
            float hn = ov * tanhf(cn);

            bool mt = r ? mt1 : mt0;
            if (mt) { c_reg[k] = cn; h_reg[k] = hn; }
            hout[k] = mt ? hn : 0.f;

            int b  = r ? b1 : b0;
            int hh = hhbase + (k & 1);
            hdst[b * NH + hh] = f2tf(h_reg[k]);
        }

        bar_arrive(grp, leaf);          // fence drains only the h stores

        // ---- hidden in the poll window: outp stores + next-step gx prefetch ----
#pragma unroll
        for (int k = 0; k < 4; k++) {
            int b  = (k >> 1) ? b1 : b0;
            int hh = hhbase + (k & 1);
            outp[(size_t)(b * NT + t_data) * (2 * NH) + dir * NH + hh] = hout[k];
        }
        if (t + 1 < NT) {
            int tn = dir ? (NT - 2 - t) : (t + 1);
            size_t base0 = (size_t)(b0 * NT + tn) * NG + hhbase;
            size_t base1 = (size_t)(b1 * NT + tn) * NG + hhbase;
#pragma unroll
            for (int g = 0; g < 4; g++) {
                float2 v0 = *(const float2*)&gxp[base0 + g * NH];
                float2 v1 = *(const float2*)&gxp[base1 + g * NH];
                gxv[g][0] = v0.x; gxv[g][1] = v0.y;
                gxv[g][2] = v1.x; gxv[g][3] = v1.y;
            }
        }

        bar_wait(grp, gen); gen++;
    }
}

// ---------------- emission FC ---------------------------------------------------
__global__ void emis_kernel(const float* __restrict__ fw, const float* __restrict__ fb)
{
    int gtid = blockIdx.x * blockDim.x + threadIdx.x;
    int w = gtid >> 5;
    int lane = threadIdx.x & 31;
    if (w >= MROWS) return;
    const float* x = g_out1 + (size_t)w * (2 * NH);
    float acc[NC];
#pragma unroll
    for (int c = 0; c < NC; c++) acc[c] = 0.f;
    for (int k = lane; k < 2 * NH; k += 32) {
        float xv = x[k];
#pragma unroll
        for (int c = 0; c < NC; c++) acc[c] += xv * fw[c * 2 * NH + k];
    }
#pragma unroll
    for (int off = 16; off > 0; off >>= 1)
#pragma unroll
        for (int c = 0; c < NC; c++) acc[c] += __shfl_down_sync(0xffffffffu, acc[c], off);
    if (lane == 0) {
#pragma unroll
        for (int c = 0; c < NC; c++) g_emis[(size_t)w * NC + c] = acc[c] + fb[c];
    }
}

// ---------------- CRF -----------------------------------------------------------
__global__ void crf_kernel(const int* __restrict__ seq_len, const int* __restrict__ tags,
                           const float* __restrict__ trans, float* __restrict__ out)
{
    int b = blockIdx.x;
    int lane = threadIdx.x;
    __shared__ float tr[NC][NC + 1];
    __shared__ float vs[NC + 1], fs[NC + 1], vf[NC + 1], ff[NC + 1];

    for (int i = lane; i < NC * NC; i += 32) tr[i / NC][i % NC] = trans[i];
    if (lane < NC) { vs[lane] = 0.f; fs[lane] = NEGV; }
    __syncwarp();

    int sl = seq_len[b];
    for (int t = 0; t < NT; t++) {
        float vnew = 0.f, fnew = 0.f;
        if (lane < NC) {
            float emi = g_emis[(size_t)(b * NT + t) * NC + lane];
            float best = vs[0] + tr[0][lane]; int bi = 0;
            float m = fs[0] + tr[0][lane];
#pragma unroll
            for (int i = 1; i < NC; i++) {
                float v = vs[i] + tr[i][lane];
                if (v > best) { best = v; bi = i; }
                float fv = fs[i] + tr[i][lane];
                if (fv > m) m = fv;
            }
            float s = 0.f;
#pragma unroll
            for (int i = 0; i < NC; i++) s += expf(fs[i] + tr[i][lane] - m);
            vnew = best + emi;
            fnew = emi + m + logf(s);
            g_bt[(size_t)(b * NT + t) * NC + lane] = (unsigned char)bi;
        }
        __syncwarp();
        if (lane < NC && t < sl) { vs[lane] = vnew; fs[lane] = fnew; }
        __syncwarp();
    }
    if (lane < NC) {
        vf[lane] = vs[lane] + tr[lane][TSTOP];
        ff[lane] = fs[lane] + tr[lane][TSTOP];
    }
    __syncwarp();
    if (lane == 0) {
        int best = 0; float bv = vf[0];
        for (int j = 1; j < NC; j++) if (vf[j] > bv) { bv = vf[j]; best = j; }
        float m = ff[0];
        for (int j = 1; j < NC; j++) if (ff[j] > m) m = ff[j];
        float s = 0.f;
        for (int j = 0; j < NC; j++) s += expf(ff[j] - m);
        float fwd = m + logf(s);

        float gold = 0.f; int prev = TSTART;
        for (int t = 0; t < sl; t++) {
            int tg = tags[b * NT + t];
            gold += g_emis[(size_t)(b * NT + t) * NC + tg] + tr[prev][tg];
            prev = tg;
        }
        gold += tr[prev][TSTOP];
        g_lossb[b] = fwd - gold;

        int cur = best;
        for (int l = NT - 1; l >= 0; l--) {
            out[b * NT + l] = (l < sl) ? (float)cur : 0.f;
            if (l >= 1 && l <= sl - 1) cur = g_bt[(size_t)(b * NT + l) * NC + cur];
        }
    }
}

__global__ void loss_reduce(float* __restrict__ out)
{
    __shared__ float s[NB];
    int i = threadIdx.x;
    s[i] = g_lossb[i];
    __syncthreads();
    for (int off = NB / 2; off > 0; off >>= 1) {
        if (i < off) s[i] += s[i + off];
        __syncthreads();
    }
    if (i == 0) out[MROWS] = s[0] / (float)NB;
}

// ---------------- launcher ------------------------------------------------------
extern "C" void kernel_launch(void* const* d_in, const int* in_sizes, int n_in,
                              void* d_out, int out_size)
{
    const int*   tokens   = (const int*)d_in[0];
    const int*   seq_len  = (const int*)d_in[1];
    const int*   tags     = (const int*)d_in[3];
    const float* emb      = (const float*)d_in[4];
    const float* w_ih_l0  = (const float*)d_in[5];
    const float* w_hh_l0  = (const float*)d_in[6];
    const float* b_ih_l0  = (const float*)d_in[7];
    const float* b_hh_l0  = (const float*)d_in[8];
    const float* w_ih_l0r = (const float*)d_in[9];
    const float* w_hh_l0r = (const float*)d_in[10];
    const float* b_ih_l0r = (const float*)d_in[11];
    const float* b_hh_l0r = (const float*)d_in[12];
    const float* w_ih_l1  = (const float*)d_in[13];
    const float* w_hh_l1  = (const float*)d_in[14];
    const float* b_ih_l1  = (const float*)d_in[15];
    const float* b_hh_l1  = (const float*)d_in[16];
    const float* w_ih_l1r = (const float*)d_in[17];
    const float* w_hh_l1r = (const float*)d_in[18];
    const float* b_ih_l1r = (const float*)d_in[19];
    const float* b_hh_l1r = (const float*)d_in[20];
    const float* fc_w     = (const float*)d_in[21];
    const float* fc_b     = (const float*)d_in[22];
    const float* trans    = (const float*)d_in[23];
    float* out = (float*)d_out;

    static int smem_set = 0;
    if (!smem_set) {
        cudaFuncSetAttribute(lstm_persist_tc,
                             cudaFuncAttributeMaxDynamicSharedMemorySize, LSTM_SMEM);
        smem_set = 1;
    }

    dim3 ggx(NG / 128, MROWS / 128, 2);

    reset_bar<<<1, 256>>>();

    // ---- layer 0 ----
    gx_gemm_tc<<<ggx, 256>>>(emb, tokens,
                             w_ih_l0, b_ih_l0, b_hh_l0,
                             w_ih_l0r, b_ih_l0r, b_hh_l0r, NE, 1);
    lstm_persist_tc<<<NBLK, 256, LSTM_SMEM>>>(seq_len, w_hh_l0, w_hh_l0r, 0);

    // ---- layer 1 ----
    gx_gemm_tc<<<ggx, 256>>>(emb, tokens,
                             w_ih_l1, b_ih_l1, b_hh_l1,
                             w_ih_l1r, b_ih_l1r, b_hh_l1r, 2 * NH, 0);
    lstm_persist_tc<<<NBLK, 256, LSTM_SMEM>>>(seq_len, w_hh_l1, w_hh_l1r, 1);

    // ---- emissions + CRF ----
    emis_kernel<<<MROWS / 8, 256>>>(fc_w, fc_b);
    crf_kernel<<<NB, 32>>>(seq_len, tags, trans, out);
    loss_reduce<<<1, 128>>>(out);
}

// round 14
// speedup vs baseline: 1.6791x; 1.1161x over previous
#include <cuda_runtime.h>
#include <math.h>

#define NB 128
#define NT 256
#define NE 300
#define NH 512
#define NG 2048     // 4*NH
#define NC 11
#define TSTART 9
#define TSTOP 10
#define NEGV -100000.0f
#define MROWS (NB*NT)   // 32768
#define NBLK 128        // persistent grid size

// ---------------- scratch (static device memory; no allocations) ----------------
__device__ float g_gxf[(size_t)MROWS * NG];       // forward-dir input projection
__device__ float g_gxr[(size_t)MROWS * NG];       // reverse-dir input projection
__device__ float g_out0[(size_t)MROWS * 2 * NH];  // layer0 output (concat fwd|bwd)
__device__ float g_out1[(size_t)MROWS * 2 * NH];  // layer1 output
__device__ unsigned g_hbf[2 * 2 * NB * (NH / 2)]; // ping-pong h, packed bf16x2
__device__ float g_emis[(size_t)MROWS * NC];
__device__ unsigned char g_bt[(size_t)MROWS * NC];
__device__ float g_lossb[NB];

// ---------------- two-level tree barrier, one per direction group ---------------
// R10-proven: ONLY thread 0 of each block touches global sync state.
__device__ unsigned g_leafc[8 * 32];     // 128B apart
__device__ unsigned g_rootc[2 * 32];
__device__ volatile unsigned g_genv[2 * 32];

__global__ void reset_bar()
{
    int i = threadIdx.x;
    if (i < 256) ((unsigned*)g_leafc)[i] = 0u;
    if (i < 64)  ((unsigned*)g_rootc)[i] = 0u;
    if (i < 64)  ((unsigned*)g_genv)[i]  = 0u;
}

__device__ __forceinline__ void bar_arrive(int grp, int leaf)
{
    __syncthreads();                       // all block stores issued
    if (threadIdx.x == 0) {
        __threadfence();                   // h stores visible device-wide
        unsigned p = atomicAdd(&g_leafc[leaf * 32], 1u);
        if ((p & 15u) == 15u) {
            unsigned q = atomicAdd(&g_rootc[grp * 32], 1u);
            if ((q & 3u) == 3u) {
                __threadfence();
                g_genv[grp * 32] = (q >> 2) + 1u;   // gen counter
            }
        }
    }
}

__device__ __forceinline__ void bar_wait(int grp, unsigned my)
{
    if (threadIdx.x == 0) {
        while (g_genv[grp * 32] <= my) { }
    }
    __syncthreads();
    // no post-wake fence: cross-block data (h) is read via cp.async.cg (L2-direct);
    // all L1-cached loads (gx, seq_len, weights) are immutable.
}

// ---------------- numeric helpers -----------------------------------------------
__device__ __forceinline__ unsigned pack_bf16x2(float lo, float hi)
{
    unsigned r;
    asm("cvt.rn.bf16x2.f32 %0, %1, %2;" : "=r"(r) : "f"(hi), "f"(lo));
    return r;
}

__device__ __forceinline__ void mma_tf32(float* d, const unsigned* a, const unsigned* b)
{
    asm volatile(
        "mma.sync.aligned.m16n8k8.row.col.f32.tf32.tf32.f32 "
        "{%0,%1,%2,%3}, {%4,%5,%6,%7}, {%8,%9}, {%0,%1,%2,%3};\n"
        : "+f"(d[0]), "+f"(d[1]), "+f"(d[2]), "+f"(d[3])
        : "r"(a[0]), "r"(a[1]), "r"(a[2]), "r"(a[3]), "r"(b[0]), "r"(b[1]));
}

__device__ __forceinline__ void mma_bf16(float* d, const unsigned* a, const unsigned* b)
{
    asm volatile(
        "mma.sync.aligned.m16n8k16.row.col.f32.bf16.bf16.f32 "
        "{%0,%1,%2,%3}, {%4,%5,%6,%7}, {%8,%9}, {%0,%1,%2,%3};\n"
        : "+f"(d[0]), "+f"(d[1]), "+f"(d[2]), "+f"(d[3])
        : "r"(a[0]), "r"(a[1]), "r"(a[2]), "r"(a[3]), "r"(b[0]), "r"(b[1]));
}

// ---------------- tf32 gx GEMM with cp.async double buffering (R13, proven) -----
#define GXS 20   // row stride in u32
__global__ __launch_bounds__(256) void gx_gemm_tc(
    const float* __restrict__ emb, const int* __restrict__ tokens,
    const float* __restrict__ W0, const float* __restrict__ bi0, const float* __restrict__ bh0,
    const float* __restrict__ W1, const float* __restrict__ bi1, const float* __restrict__ bh1,
    int K, int gather)
{
    int dir = blockIdx.z;
    const float* W  = dir ? W1  : W0;
    const float* bi = dir ? bi1 : bi0;
    const float* bh = dir ? bh1 : bh0;
    float* out = dir ? g_gxr : g_gxf;

    __shared__ unsigned As[2][128 * GXS];
    __shared__ unsigned Bs[2][128 * GXS];

    int tid  = threadIdx.x;
    int warp = tid >> 5;
    int lane = tid & 31;
    int quad = lane >> 2;
    int l4   = lane & 3;
    int wm   = (warp >> 1) * 32;
    int wn   = (warp & 1) * 64;

    int m0 = blockIdx.y * 128;
    int n0 = blockIdx.x * 128;

    float acc[2][8][4];
#pragma unroll
    for (int i = 0; i < 2; i++)
#pragma unroll
        for (int j = 0; j < 8; j++)
#pragma unroll
            for (int q = 0; q < 4; q++) acc[i][j][q] = 0.f;

    int kiters = (K + 15) >> 4;

    auto do_stage = [&](int buf, int kt) {
        int k0 = kt << 4;
#pragma unroll
        for (int r = 0; r < 2; r++) {
            int f  = tid + 256 * r;
            int mm = f >> 2;
            int c4 = (f & 3) * 4;
            int k  = k0 + c4;
            int row = m0 + mm;
            const float* src = gather ? (emb + (size_t)tokens[row] * NE + k)
                                      : (g_out0 + (size_t)row * (2 * NH) + k);
            int nb = (K - k) * 4; nb = nb < 0 ? 0 : (nb > 16 ? 16 : nb);
            unsigned d = (unsigned)__cvta_generic_to_shared(&As[buf][mm * GXS + c4]);
            asm volatile("cp.async.cg.shared.global [%0], [%1], 16, %2;"
                         :: "r"(d), "l"(src), "r"(nb));
        }
#pragma unroll
        for (int r = 0; r < 2; r++) {
            int f  = tid + 256 * r;
            int nn = f >> 2;
            int c4 = (f & 3) * 4;
            int k  = k0 + c4;
            const float* src = W + (size_t)(n0 + nn) * K + k;
            int nb = (K - k) * 4; nb = nb < 0 ? 0 : (nb > 16 ? 16 : nb);
            unsigned d = (unsigned)__cvta_generic_to_shared(&Bs[buf][nn * GXS + c4]);
            asm volatile("cp.async.cg.shared.global [%0], [%1], 16, %2;"
                         :: "r"(d), "l"(src), "r"(nb));
        }
        asm volatile("cp.async.commit_group;");
    };

    do_stage(0, 0);

    for (int kt = 0; kt < kiters; kt++) {
        int buf = kt & 1;
        if (kt + 1 < kiters) {
            do_stage(buf ^ 1, kt + 1);
            asm volatile("cp.async.wait_group 1;");
        } else {
            asm volatile("cp.async.wait_group 0;");
        }
        __syncthreads();

        const unsigned* Ab = As[buf];
        const unsigned* Bb = Bs[buf];
#pragma unroll
        for (int ks = 0; ks < 16; ks += 8) {
            unsigned a[2][4], b[8][2];
#pragma unroll
            for (int mt = 0; mt < 2; mt++) {
                int mb = wm + mt * 16;
                a[mt][0] = Ab[(mb + quad) * GXS + ks + l4];
                a[mt][1] = Ab[(mb + quad + 8) * GXS + ks + l4];
                a[mt][2] = Ab[(mb + quad) * GXS + ks + l4 + 4];
                a[mt][3] = Ab[(mb + quad + 8) * GXS + ks + l4 + 4];
            }
#pragma unroll
            for (int nt = 0; nt < 8; nt++) {
                int nb = wn + nt * 8;
                b[nt][0] = Bb[(nb + quad) * GXS + ks + l4];
                b[nt][1] = Bb[(nb + quad) * GXS + ks + l4 + 4];
            }
#pragma unroll
            for (int mt = 0; mt < 2; mt++)
#pragma unroll
                for (int nt = 0; nt < 8; nt++)
                    mma_tf32(acc[mt][nt], a[mt], b[nt]);
        }
        __syncthreads();
    }

#pragma unroll
    for (int mt = 0; mt < 2; mt++) {
        int r0 = m0 + wm + mt * 16 + quad;
#pragma unroll
        for (int nt = 0; nt < 8; nt++) {
            int col = n0 + wn + nt * 8 + l4 * 2;
            float bsum0 = bi[col] + bh[col];
            float bsum1 = bi[col + 1] + bh[col + 1];
            float2 v0 = make_float2(acc[mt][nt][0] + bsum0, acc[mt][nt][1] + bsum1);
            float2 v1 = make_float2(acc[mt][nt][2] + bsum0, acc[mt][nt][3] + bsum1);
            *(float2*)&out[(size_t)r0 * NG + col] = v0;
            *(float2*)&out[(size_t)(r0 + 8) * NG + col] = v1;
        }
    }
}

// ---------------- bf16 tensor-core persistent bidirectional LSTM ----------------
// h packed bf16x2 (halves the per-step L2 broadcast); W resident in smem as
// bf16x2 pairs over k; mma.m16n8k16 (K=16/inst). Barrier/pipeline = R10 proven.
#define WSS2 40  // Wsm row stride (u32, rows = k2=0..255): bank = 8*l4+quad+8*g, CF
#define HSS2 36  // hs row stride (u32, rows = batch):      bank = 4*quad+l4, CF
#define WS2_U (256 * WSS2)      // 10240 u32
#define HS2_U (NB * HSS2)       // 4608 u32 per buffer
#define LSTM_SMEM ((WS2_U + 2 * HS2_U) * 4)   // 77824 bytes

__device__ __forceinline__ void stage_chunk(const unsigned* __restrict__ hsrc,
                                            unsigned* __restrict__ dstbase,
                                            int chunk, int tid)
{
    // chunk covers h cols [64c, 64c+64) = u32 pairs [32c, 32c+32): 128B/row = 8 segs
#pragma unroll
    for (int r = 0; r < 4; r++) {
        int f   = tid + 256 * r;       // 0..1023 16B segments
        int row = f >> 3;
        int seg = f & 7;
        unsigned daddr = (unsigned)__cvta_generic_to_shared(dstbase + row * HSS2 + seg * 4);
        const unsigned* src = hsrc + row * (NH / 2) + chunk * 32 + seg * 4;
        asm volatile("cp.async.cg.shared.global [%0], [%1], 16;" :: "r"(daddr), "l"(src));
    }
}

__global__ __launch_bounds__(256) void lstm_persist_tc(
    const int* __restrict__ seq_len,
    const float* __restrict__ Whf, const float* __restrict__ Whr,
    int layer)
{
    extern __shared__ unsigned usmem[];
    unsigned* Wsm = usmem;              // [256 k2][40] bf16x2 Whh slice
    unsigned* hs0 = usmem + WS2_U;      // chunk buffer 0: [128][36]
    unsigned* hs1 = hs0 + HS2_U;        // chunk buffer 1

    int tid  = threadIdx.x;
    int bid  = blockIdx.x;
    int dir  = bid >> 6;
    int hc0  = (bid & 63) * 8;
    int grp  = dir;                     // barrier group per direction
    int leaf = bid >> 4;                // 0..7, 4 per group

    int w    = tid >> 5;
    int lane = tid & 31;
    int quad = lane >> 2;
    int l4   = lane & 3;

    const float* W   = dir ? Whr : Whf;
    const float* gxp = dir ? g_gxr : g_gxf;
    float* outp = layer ? g_out1 : g_out0;

    unsigned gen = g_genv[grp * 32];    // stable at launch boundary

    // resident Whh slice -> bf16x2 smem: Wsm[k2*WSS2 + c] = pack(W[col][2k2], W[col][2k2+1])
    for (int jj = tid; jj < 32 * 256; jj += 256) {
        int c = jj >> 8, k2 = jj & 255;
        int g = c >> 3, j = c & 7;
        const float* wr = W + (size_t)(g * NH + hc0 + j) * NH + 2 * k2;
        Wsm[k2 * WSS2 + c] = pack_bf16x2(wr[0], wr[1]);
    }

    // zero h ping buffer 0 (ping0 = 65536 u32; each block zeroes 512)
#pragma unroll
    for (int i = 0; i < 2; i++)
        g_hbf[bid * 512 + i * 256 + tid] = 0u;

    int b0 = 16 * w + quad;
    int b1 = b0 + 8;
    int hhbase = hc0 + 2 * l4;          // even
    int sl0 = seq_len[b0];
    int sl1 = seq_len[b1];
    float c_reg[4] = {0.f, 0.f, 0.f, 0.f};
    float h_reg[4] = {0.f, 0.f, 0.f, 0.f};

    // prefetch gx for step 0 (immutable; legal before the barrier)
    float gxv[4][4];
    {
        int t_data0 = dir ? (NT - 1) : 0;
        size_t base0 = (size_t)(b0 * NT + t_data0) * NG + hhbase;
        size_t base1 = (size_t)(b1 * NT + t_data0) * NG + hhbase;
#pragma unroll
        for (int g = 0; g < 4; g++) {
            float2 v0 = *(const float2*)&gxp[base0 + g * NH];
            float2 v1 = *(const float2*)&gxp[base1 + g * NH];
            gxv[g][0] = v0.x; gxv[g][1] = v0.y;
            gxv[g][2] = v1.x; gxv[g][3] = v1.y;
        }
    }

    bar_arrive(grp, leaf);              // h zero-init visible everywhere
    bar_wait(grp, gen); gen++;

    for (int t = 0; t < NT; t++) {
        int rb = t & 1;
        int wbuf = 1 - rb;
        int t_data = dir ? (NT - 1 - t) : t;

        const unsigned* hsrc = g_hbf + rb * (2 * NB * (NH / 2)) + dir * (NB * (NH / 2));

        // kick off h chunk 0 immediately after the barrier
        stage_chunk(hsrc, hs0, 0, tid);
        asm volatile("cp.async.commit_group;");

        float acc[4][4];
#pragma unroll
        for (int g = 0; g < 4; g++)
#pragma unroll
            for (int q = 0; q < 4; q++) acc[g][q] = 0.f;

#pragma unroll
        for (int chunk = 0; chunk < 8; chunk++) {
            unsigned* cur = (chunk & 1) ? hs1 : hs0;
            if (chunk < 7) {
                unsigned* nxt = (chunk & 1) ? hs0 : hs1;
                stage_chunk(hsrc, nxt, chunk + 1, tid);
                asm volatile("cp.async.commit_group;");
                asm volatile("cp.async.wait_group 1;");
            } else {
                asm volatile("cp.async.wait_group 0;");
            }
            __syncthreads();

            int k2g0 = chunk * 32;          // global k2 base of this chunk
#pragma unroll
            for (int s = 0; s < 4; s++) {   // 16 k per mma
                int k2c = s * 8;
                unsigned a[4];
                a[0] = cur[b0 * HSS2 + k2c + l4];
                a[1] = cur[b1 * HSS2 + k2c + l4];
                a[2] = cur[b0 * HSS2 + k2c + l4 + 4];
                a[3] = cur[b1 * HSS2 + k2c + l4 + 4];
                int k2g = k2g0 + k2c;
#pragma unroll
                for (int g = 0; g < 4; g++) {
                    unsigned b[2];
                    b[0] = Wsm[(k2g + l4) * WSS2 + g * 8 + quad];
                    b[1] = Wsm[(k2g + l4 + 4) * WSS2 + g * 8 + quad];
                    mma_bf16(acc[g], a, b);
                }
            }
            __syncthreads();
        }

        // ---- Phase B: cell update; store ONLY h before arrival ----
        unsigned* hdst = g_hbf + wbuf * (2 * NB * (NH / 2)) + dir * (NB * (NH / 2));
        bool mt0 = t_data < sl0;
        bool mt1 = t_data < sl1;
        float hout[4];
#pragma unroll
        for (int k = 0; k < 4; k++) {
            int r  = k >> 1;
            float gi = acc[0][k] + gxv[0][k];
            float gf = acc[1][k] + gxv[1][k];
            float gg = acc[2][k] + gxv[2][k];
            float go = acc[3][k] + gxv[3][k];

            float iv = 1.f / (1.f + expf(-gi));
            float fv = 1.f / (1.f + expf(-gf));
            float ov = 1.f / (1.f + expf(-go));
            float gv = tanhf(gg);

            float cn = fv * c_reg[k] + iv * gv;
            float hn = ov * tanhf(cn);

            bool mt = r ? mt1 : mt0;
            if (mt) { c_reg[k] = cn; h_reg[k] = hn; }
            hout[k] = mt ? hn : 0.f;
        }
        hdst[b0 * (NH / 2) + (hhbase >> 1)] = pack_bf16x2(h_reg[0], h_reg[1]);
        hdst[b1 * (NH / 2) + (hhbase >> 1)] = pack_bf16x2(h_reg[2], h_reg[3]);

        bar_arrive(grp, leaf);          // fence drains only the h stores

        // ---- hidden in the poll window: outp stores + next-step gx prefetch ----
#pragma unroll
        for (int k = 0; k < 4; k++) {
            int b  = (k >> 1) ? b1 : b0;
            int hh = hhbase + (k & 1);
            outp[(size_t)(b * NT + t_data) * (2 * NH) + dir * NH + hh] = hout[k];
        }
        if (t + 1 < NT) {
            int tn = dir ? (NT - 2 - t) : (t + 1);
            size_t base0 = (size_t)(b0 * NT + tn) * NG + hhbase;
            size_t base1 = (size_t)(b1 * NT + tn) * NG + hhbase;
#pragma unroll
            for (int g = 0; g < 4; g++) {
                float2 v0 = *(const float2*)&gxp[base0 + g * NH];
                float2 v1 = *(const float2*)&gxp[base1 + g * NH];
                gxv[g][0] = v0.x; gxv[g][1] = v0.y;
                gxv[g][2] = v1.x; gxv[g][3] = v1.y;
            }
        }

        bar_wait(grp, gen); gen++;
    }
}

// ---------------- emission FC ---------------------------------------------------
__global__ void emis_kernel(const float* __restrict__ fw, const float* __restrict__ fb)
{
    int gtid = blockIdx.x * blockDim.x + threadIdx.x;
    int w = gtid >> 5;
    int lane = threadIdx.x & 31;
    if (w >= MROWS) return;
    const float* x = g_out1 + (size_t)w * (2 * NH);
    float acc[NC];
#pragma unroll
    for (int c = 0; c < NC; c++) acc[c] = 0.f;
    for (int k = lane; k < 2 * NH; k += 32) {
        float xv = x[k];
#pragma unroll
        for (int c = 0; c < NC; c++) acc[c] += xv * fw[c * 2 * NH + k];
    }
#pragma unroll
    for (int off = 16; off > 0; off >>= 1)
#pragma unroll
        for (int c = 0; c < NC; c++) acc[c] += __shfl_down_sync(0xffffffffu, acc[c], off);
    if (lane == 0) {
#pragma unroll
        for (int c = 0; c < NC; c++) g_emis[(size_t)w * NC + c] = acc[c] + fb[c];
    }
}

// ---------------- CRF -----------------------------------------------------------
__global__ void crf_kernel(const int* __restrict__ seq_len, const int* __restrict__ tags,
                           const float* __restrict__ trans, float* __restrict__ out)
{
    int b = blockIdx.x;
    int lane = threadIdx.x;
    __shared__ float tr[NC][NC + 1];
    __shared__ float vs[NC + 1], fs[NC + 1], vf[NC + 1], ff[NC + 1];

    for (int i = lane; i < NC * NC; i += 32) tr[i / NC][i % NC] = trans[i];
    if (lane < NC) { vs[lane] = 0.f; fs[lane] = NEGV; }
    __syncwarp();

    int sl = seq_len[b];
    for (int t = 0; t < NT; t++) {
        float vnew = 0.f, fnew = 0.f;
        if (lane < NC) {
            float emi = g_emis[(size_t)(b * NT + t) * NC + lane];
            float best = vs[0] + tr[0][lane]; int bi = 0;
            float m = fs[0] + tr[0][lane];
#pragma unroll
            for (int i = 1; i < NC; i++) {
                float v = vs[i] + tr[i][lane];
                if (v > best) { best = v; bi = i; }
                float fv = fs[i] + tr[i][lane];
                if (fv > m) m = fv;
            }
            float s = 0.f;
#pragma unroll
            for (int i = 0; i < NC; i++) s += expf(fs[i] + tr[i][lane] - m);
            vnew = best + emi;
            fnew = emi + m + logf(s);
            g_bt[(size_t)(b * NT + t) * NC + lane] = (unsigned char)bi;
        }
        __syncwarp();
        if (lane < NC && t < sl) { vs[lane] = vnew; fs[lane] = fnew; }
        __syncwarp();
    }
    if (lane < NC) {
        vf[lane] = vs[lane] + tr[lane][TSTOP];
        ff[lane] = fs[lane] + tr[lane][TSTOP];
    }
    __syncwarp();
    if (lane == 0) {
        int best = 0; float bv = vf[0];
        for (int j = 1; j < NC; j++) if (vf[j] > bv) { bv = vf[j]; best = j; }
        float m = ff[0];
        for (int j = 1; j < NC; j++) if (ff[j] > m) m = ff[j];
        float s = 0.f;
        for (int j = 0; j < NC; j++) s += expf(ff[j] - m);
        float fwd = m + logf(s);

        float gold = 0.f; int prev = TSTART;
        for (int t = 0; t < sl; t++) {
            int tg = tags[b * NT + t];
            gold += g_emis[(size_t)(b * NT + t) * NC + tg] + tr[prev][tg];
            prev = tg;
        }
        gold += tr[prev][TSTOP];
        g_lossb[b] = fwd - gold;

        int cur = best;
        for (int l = NT - 1; l >= 0; l--) {
            out[b * NT + l] = (l < sl) ? (float)cur : 0.f;
            if (l >= 1 && l <= sl - 1) cur = g_bt[(size_t)(b * NT + l) * NC + cur];
        }
    }
}

__global__ void loss_reduce(float* __restrict__ out)
{
    __shared__ float s[NB];
    int i = threadIdx.x;
    s[i] = g_lossb[i];
    __syncthreads();
    for (int off = NB / 2; off > 0; off >>= 1) {
        if (i < off) s[i] += s[i + off];
        __syncthreads();
    }
    if (i == 0) out[MROWS] = s[0] / (float)NB;
}

// ---------------- launcher ------------------------------------------------------
extern "C" void kernel_launch(void* const* d_in, const int* in_sizes, int n_in,
                              void* d_out, int out_size)
{
    const int*   tokens   = (const int*)d_in[0];
    const int*   seq_len  = (const int*)d_in[1];
    const int*   tags     = (const int*)d_in[3];
    const float* emb      = (const float*)d_in[4];
    const float* w_ih_l0  = (const float*)d_in[5];
    const float* w_hh_l0  = (const float*)d_in[6];
    const float* b_ih_l0  = (const float*)d_in[7];
    const float* b_hh_l0  = (const float*)d_in[8];
    const float* w_ih_l0r = (const float*)d_in[9];
    const float* w_hh_l0r = (const float*)d_in[10];
    const float* b_ih_l0r = (const float*)d_in[11];
    const float* b_hh_l0r = (const float*)d_in[12];
    const float* w_ih_l1  = (const float*)d_in[13];
    const float* w_hh_l1  = (const float*)d_in[14];
    const float* b_ih_l1  = (const float*)d_in[15];
    const float* b_hh_l1  = (const float*)d_in[16];
    const float* w_ih_l1r = (const float*)d_in[17];
    const float* w_hh_l1r = (const float*)d_in[18];
    const float* b_ih_l1r = (const float*)d_in[19];
    const float* b_hh_l1r = (const float*)d_in[20];
    const float* fc_w     = (const float*)d_in[21];
    const float* fc_b     = (const float*)d_in[22];
    const float* trans    = (const float*)d_in[23];
    float* out = (float*)d_out;

    static int smem_set = 0;
    if (!smem_set) {
        cudaFuncSetAttribute(lstm_persist_tc,
                             cudaFuncAttributeMaxDynamicSharedMemorySize, LSTM_SMEM);
        smem_set = 1;
    }

    dim3 ggx(NG / 128, MROWS / 128, 2);

    reset_bar<<<1, 256>>>();

    // ---- layer 0 ----
    gx_gemm_tc<<<ggx, 256>>>(emb, tokens,
                             w_ih_l0, b_ih_l0, b_hh_l0,
                             w_ih_l0r, b_ih_l0r, b_hh_l0r, NE, 1);
    lstm_persist_tc<<<NBLK, 256, LSTM_SMEM>>>(seq_len, w_hh_l0, w_hh_l0r, 0);

    // ---- layer 1 ----
    gx_gemm_tc<<<ggx, 256>>>(emb, tokens,
                             w_ih_l1, b_ih_l1, b_hh_l1,
                             w_ih_l1r, b_ih_l1r, b_hh_l1r, 2 * NH, 0);
    lstm_persist_tc<<<NBLK, 256, LSTM_SMEM>>>(seq_len, w_hh_l1, w_hh_l1r, 1);

    // ---- emissions + CRF ----
    emis_kernel<<<MROWS / 8, 256>>>(fc_w, fc_b);
    crf_kernel<<<NB, 32>>>(seq_len, tags, trans, out);
    loss_reduce<<<1, 128>>>(out);
}

// round 15
// speedup vs baseline: 2.0518x; 1.2220x over previous
#include <cuda_runtime.h>
#include <math.h>

#define NB 128
#define NT 256
#define NE 300
#define NEP 320     // padded embedding K (zero-fill)
#define NH 512
#define NG 2048     // 4*NH
#define NC 11
#define TSTART 9
#define TSTOP 10
#define NEGV -100000.0f
#define MROWS (NB*NT)   // 32768
#define NBLK 128        // persistent grid size
#define NV 50000

// ---------------- scratch (static device memory; no allocations) ----------------
__device__ float g_gxf[(size_t)MROWS * NG];       // forward-dir input projection (fp32)
__device__ float g_gxr[(size_t)MROWS * NG];       // reverse-dir input projection (fp32)
__device__ unsigned g_outbf0[(size_t)MROWS * (NH)];   // layer0 out, bf16x2 [row][1024c/2]
__device__ unsigned g_outbf1[(size_t)MROWS * (NH)];   // layer1 out, bf16x2
__device__ unsigned g_hbf[2 * 2 * NB * (NH / 2)]; // ping-pong h, packed bf16x2
__device__ unsigned g_embbf[(size_t)NV * (NEP / 2)];  // bf16x2 embedding table, padded
__device__ unsigned g_wbf0[2][(size_t)NG * (NEP / 2)];   // bf16x2 w_ih l0 / l0r
__device__ unsigned g_wbf1[2][(size_t)NG * (2 * NH / 2)];// bf16x2 w_ih l1 / l1r
__device__ float g_emis[(size_t)MROWS * NC];
__device__ unsigned char g_bt[(size_t)MROWS * NC];
__device__ float g_lossb[NB];

// ---------------- two-level tree barrier (R10-proven) ---------------------------
__device__ unsigned g_leafc[8 * 32];
__device__ unsigned g_rootc[2 * 32];
__device__ volatile unsigned g_genv[2 * 32];

__global__ void reset_bar()
{
    int i = threadIdx.x;
    if (i < 256) ((unsigned*)g_leafc)[i] = 0u;
    if (i < 64)  ((unsigned*)g_rootc)[i] = 0u;
    if (i < 64)  ((unsigned*)g_genv)[i]  = 0u;
}

__device__ __forceinline__ void bar_arrive(int grp, int leaf)
{
    __syncthreads();
    if (threadIdx.x == 0) {
        __threadfence();
        unsigned p = atomicAdd(&g_leafc[leaf * 32], 1u);
        if ((p & 15u) == 15u) {
            unsigned q = atomicAdd(&g_rootc[grp * 32], 1u);
            if ((q & 3u) == 3u) {
                __threadfence();
                g_genv[grp * 32] = (q >> 2) + 1u;
            }
        }
    }
}

__device__ __forceinline__ void bar_wait(int grp, unsigned my)
{
    if (threadIdx.x == 0) {
        while (g_genv[grp * 32] <= my) { }
    }
    __syncthreads();
}

// ---------------- numeric helpers -----------------------------------------------
__device__ __forceinline__ unsigned pack_bf16x2(float lo, float hi)
{
    unsigned r;
    asm("cvt.rn.bf16x2.f32 %0, %1, %2;" : "=r"(r) : "f"(hi), "f"(lo));
    return r;
}

__device__ __forceinline__ void mma_bf16(float* d, const unsigned* a, const unsigned* b)
{
    asm volatile(
        "mma.sync.aligned.m16n8k16.row.col.f32.bf16.bf16.f32 "
        "{%0,%1,%2,%3}, {%4,%5,%6,%7}, {%8,%9}, {%0,%1,%2,%3};\n"
        : "+f"(d[0]), "+f"(d[1]), "+f"(d[2]), "+f"(d[3])
        : "r"(a[0]), "r"(a[1]), "r"(a[2]), "r"(a[3]), "r"(b[0]), "r"(b[1]));
}

// ---------------- conversion kernels (run each replay; deterministic) -----------
__global__ void conv_emb(const float* __restrict__ emb)
{
    size_t i = (size_t)blockIdx.x * 256 + threadIdx.x;     // over NV * 160
    if (i >= (size_t)NV * (NEP / 2)) return;
    int c2  = (int)(i % (NEP / 2));
    size_t row = i / (NEP / 2);
    int c = 2 * c2;
    float lo = (c < NE)     ? emb[row * NE + c]     : 0.f;
    float hi = (c + 1 < NE) ? emb[row * NE + c + 1] : 0.f;
    g_embbf[i] = pack_bf16x2(lo, hi);
}

__global__ void conv_w(const float* __restrict__ W, unsigned* __restrict__ dst,
                       int K, int Kp2)
{
    size_t i = (size_t)blockIdx.x * 256 + threadIdx.x;     // over NG * Kp2
    if (i >= (size_t)NG * Kp2) return;
    int c2  = (int)(i % Kp2);
    size_t row = i / Kp2;
    int c = 2 * c2;
    float lo = (c < K)     ? W[row * K + c]     : 0.f;
    float hi = (c + 1 < K) ? W[row * K + c + 1] : 0.f;
    dst[i] = pack_bf16x2(lo, hi);
}

// ---------------- bf16 gx GEMM with cp.async double buffering -------------------
// Same structure/addressing as the R13 tf32 kernel (stride-20 smem rows, proven
// conflict-free) but bf16x2 data: half the kiters, traffic, and mma count.
// K padded to a multiple of 32 with zeros -> no tail handling.
#define GXS 20   // row stride in u32 (16 used = 32 bf16 k)
__global__ __launch_bounds__(256) void gx_gemm_bf16(
    const int* __restrict__ tokens,
    const unsigned* __restrict__ Wb0, const float* __restrict__ bi0, const float* __restrict__ bh0,
    const unsigned* __restrict__ Wb1, const float* __restrict__ bi1, const float* __restrict__ bh1,
    int Kp2, int gather)    // Kp2 = padded K in u32 pairs (160 or 512)
{
    int dir = blockIdx.z;
    const unsigned* W = dir ? Wb1 : Wb0;
    const float* bi = dir ? bi1 : bi0;
    const float* bh = dir ? bh1 : bh0;
    float* out = dir ? g_gxr : g_gxf;

    __shared__ unsigned As[2][128 * GXS];
    __shared__ unsigned Bs[2][128 * GXS];

    int tid  = threadIdx.x;
    int warp = tid >> 5;
    int lane = tid & 31;
    int quad = lane >> 2;
    int l4   = lane & 3;
    int wm   = (warp >> 1) * 32;
    int wn   = (warp & 1) * 64;

    int m0 = blockIdx.y * 128;
    int n0 = blockIdx.x * 128;

    float acc[2][8][4];
#pragma unroll
    for (int i = 0; i < 2; i++)
#pragma unroll
        for (int j = 0; j < 8; j++)
#pragma unroll
            for (int q = 0; q < 4; q++) acc[i][j][q] = 0.f;

    int kiters = Kp2 >> 4;   // 16 u32 (=32 bf16) per tile

    auto do_stage = [&](int buf, int kt) {
        int k2_0 = kt << 4;
#pragma unroll
        for (int r = 0; r < 2; r++) {
            int f  = tid + 256 * r;
            int mm = f >> 2;
            int sg = (f & 3) * 4;
            int row = m0 + mm;
            const unsigned* src = gather
                ? (g_embbf + (size_t)tokens[row] * (NEP / 2) + k2_0 + sg)
                : (g_outbf0 + (size_t)row * NH + k2_0 + sg);
            unsigned d = (unsigned)__cvta_generic_to_shared(&As[buf][mm * GXS + sg]);
            asm volatile("cp.async.cg.shared.global [%0], [%1], 16;" :: "r"(d), "l"(src));
        }
#pragma unroll
        for (int r = 0; r < 2; r++) {
            int f  = tid + 256 * r;
            int nn = f >> 2;
            int sg = (f & 3) * 4;
            const unsigned* src = W + (size_t)(n0 + nn) * Kp2 + k2_0 + sg;
            unsigned d = (unsigned)__cvta_generic_to_shared(&Bs[buf][nn * GXS + sg]);
            asm volatile("cp.async.cg.shared.global [%0], [%1], 16;" :: "r"(d), "l"(src));
        }
        asm volatile("cp.async.commit_group;");
    };

    do_stage(0, 0);

    for (int kt = 0; kt < kiters; kt++) {
        int buf = kt & 1;
        if (kt + 1 < kiters) {
            do_stage(buf ^ 1, kt + 1);
            asm volatile("cp.async.wait_group 1;");
        } else {
            asm volatile("cp.async.wait_group 0;");
        }
        __syncthreads();

        const unsigned* Ab = As[buf];
        const unsigned* Bb = Bs[buf];
#pragma unroll
        for (int kg = 0; kg < 16; kg += 8) {
            unsigned a[2][4], b[8][2];
#pragma unroll
            for (int mt = 0; mt < 2; mt++) {
                int mb = wm + mt * 16;
                a[mt][0] = Ab[(mb + quad) * GXS + kg + l4];
                a[mt][1] = Ab[(mb + quad + 8) * GXS + kg + l4];
                a[mt][2] = Ab[(mb + quad) * GXS + kg + l4 + 4];
                a[mt][3] = Ab[(mb + quad + 8) * GXS + kg + l4 + 4];
            }
#pragma unroll
            for (int nt = 0; nt < 8; nt++) {
                int nb = wn + nt * 8;
                b[nt][0] = Bb[(nb + quad) * GXS + kg + l4];
                b[nt][1] = Bb[(nb + quad) * GXS + kg + l4 + 4];
            }
#pragma unroll
            for (int mt = 0; mt < 2; mt++)
#pragma unroll
                for (int nt = 0; nt < 8; nt++)
                    mma_bf16(acc[mt][nt], a[mt], b[nt]);
        }
        __syncthreads();
    }

#pragma unroll
    for (int mt = 0; mt < 2; mt++) {
        int r0 = m0 + wm + mt * 16 + quad;
#pragma unroll
        for (int nt = 0; nt < 8; nt++) {
            int col = n0 + wn + nt * 8 + l4 * 2;
            float bsum0 = bi[col] + bh[col];
            float bsum1 = bi[col + 1] + bh[col + 1];
            float2 v0 = make_float2(acc[mt][nt][0] + bsum0, acc[mt][nt][1] + bsum1);
            float2 v1 = make_float2(acc[mt][nt][2] + bsum0, acc[mt][nt][3] + bsum1);
            *(float2*)&out[(size_t)r0 * NG + col] = v0;
            *(float2*)&out[(size_t)(r0 + 8) * NG + col] = v1;
        }
    }
}

// ---------------- bf16 tensor-core persistent bidirectional LSTM (R14 proven) --
#define WSS2 40
#define HSS2 36
#define WS2_U (256 * WSS2)
#define HS2_U (NB * HSS2)
#define LSTM_SMEM ((WS2_U + 2 * HS2_U) * 4)   // 77824 bytes

__device__ __forceinline__ void stage_chunk(const unsigned* __restrict__ hsrc,
                                            unsigned* __restrict__ dstbase,
                                            int chunk, int tid)
{
#pragma unroll
    for (int r = 0; r < 4; r++) {
        int f   = tid + 256 * r;
        int row = f >> 3;
        int seg = f & 7;
        unsigned daddr = (unsigned)__cvta_generic_to_shared(dstbase + row * HSS2 + seg * 4);
        const unsigned* src = hsrc + row * (NH / 2) + chunk * 32 + seg * 4;
        asm volatile("cp.async.cg.shared.global [%0], [%1], 16;" :: "r"(daddr), "l"(src));
    }
}

__global__ __launch_bounds__(256) void lstm_persist_tc(
    const int* __restrict__ seq_len,
    const float* __restrict__ Whf, const float* __restrict__ Whr,
    int layer)
{
    extern __shared__ unsigned usmem[];
    unsigned* Wsm = usmem;
    unsigned* hs0 = usmem + WS2_U;
    unsigned* hs1 = hs0 + HS2_U;

    int tid  = threadIdx.x;
    int bid  = blockIdx.x;
    int dir  = bid >> 6;
    int hc0  = (bid & 63) * 8;
    int grp  = dir;
    int leaf = bid >> 4;

    int w    = tid >> 5;
    int lane = tid & 31;
    int quad = lane >> 2;
    int l4   = lane & 3;

    const float* W   = dir ? Whr : Whf;
    const float* gxp = dir ? g_gxr : g_gxf;
    unsigned* outp = layer ? g_outbf1 : g_outbf0;

    unsigned gen = g_genv[grp * 32];

    for (int jj = tid; jj < 32 * 256; jj += 256) {
        int c = jj >> 8, k2 = jj & 255;
        int g = c >> 3, j = c & 7;
        const float* wr = W + (size_t)(g * NH + hc0 + j) * NH + 2 * k2;
        Wsm[k2 * WSS2 + c] = pack_bf16x2(wr[0], wr[1]);
    }

#pragma unroll
    for (int i = 0; i < 2; i++)
        g_hbf[bid * 512 + i * 256 + tid] = 0u;

    int b0 = 16 * w + quad;
    int b1 = b0 + 8;
    int hhbase = hc0 + 2 * l4;
    int sl0 = seq_len[b0];
    int sl1 = seq_len[b1];
    float c_reg[4] = {0.f, 0.f, 0.f, 0.f};
    float h_reg[4] = {0.f, 0.f, 0.f, 0.f};

    float gxv[4][4];
    {
        int t_data0 = dir ? (NT - 1) : 0;
        size_t base0 = (size_t)(b0 * NT + t_data0) * NG + hhbase;
        size_t base1 = (size_t)(b1 * NT + t_data0) * NG + hhbase;
#pragma unroll
        for (int g = 0; g < 4; g++) {
            float2 v0 = *(const float2*)&gxp[base0 + g * NH];
            float2 v1 = *(const float2*)&gxp[base1 + g * NH];
            gxv[g][0] = v0.x; gxv[g][1] = v0.y;
            gxv[g][2] = v1.x; gxv[g][3] = v1.y;
        }
    }

    bar_arrive(grp, leaf);
    bar_wait(grp, gen); gen++;

    for (int t = 0; t < NT; t++) {
        int rb = t & 1;
        int wbuf = 1 - rb;
        int t_data = dir ? (NT - 1 - t) : t;

        const unsigned* hsrc = g_hbf + rb * (2 * NB * (NH / 2)) + dir * (NB * (NH / 2));

        stage_chunk(hsrc, hs0, 0, tid);
        asm volatile("cp.async.commit_group;");

        float acc[4][4];
#pragma unroll
        for (int g = 0; g < 4; g++)
#pragma unroll
            for (int q = 0; q < 4; q++) acc[g][q] = 0.f;

#pragma unroll
        for (int chunk = 0; chunk < 8; chunk++) {
            unsigned* cur = (chunk & 1) ? hs1 : hs0;
            if (chunk < 7) {
                unsigned* nxt = (chunk & 1) ? hs0 : hs1;
                stage_chunk(hsrc, nxt, chunk + 1, tid);
                asm volatile("cp.async.commit_group;");
                asm volatile("cp.async.wait_group 1;");
            } else {
                asm volatile("cp.async.wait_group 0;");
            }
            __syncthreads();

            int k2g0 = chunk * 32;
#pragma unroll
            for (int s = 0; s < 4; s++) {
                int k2c = s * 8;
                unsigned a[4];
                a[0] = cur[b0 * HSS2 + k2c + l4];
                a[1] = cur[b1 * HSS2 + k2c + l4];
                a[2] = cur[b0 * HSS2 + k2c + l4 + 4];
                a[3] = cur[b1 * HSS2 + k2c + l4 + 4];
                int k2g = k2g0 + k2c;
#pragma unroll
                for (int g = 0; g < 4; g++) {
                    unsigned b[2];
                    b[0] = Wsm[(k2g + l4) * WSS2 + g * 8 + quad];
                    b[1] = Wsm[(k2g + l4 + 4) * WSS2 + g * 8 + quad];
                    mma_bf16(acc[g], a, b);
                }
            }
            __syncthreads();
        }

        unsigned* hdst = g_hbf + wbuf * (2 * NB * (NH / 2)) + dir * (NB * (NH / 2));
        bool mt0 = t_data < sl0;
        bool mt1 = t_data < sl1;
        float hout[4];
#pragma unroll
        for (int k = 0; k < 4; k++) {
            int r  = k >> 1;
            float gi = acc[0][k] + gxv[0][k];
            float gf = acc[1][k] + gxv[1][k];
            float gg = acc[2][k] + gxv[2][k];
            float go = acc[3][k] + gxv[3][k];

            float iv = 1.f / (1.f + expf(-gi));
            float fv = 1.f / (1.f + expf(-gf));
            float ov = 1.f / (1.f + expf(-go));
            float gv = tanhf(gg);

            float cn = fv * c_reg[k] + iv * gv;
            float hn = ov * tanhf(cn);

            bool mt = r ? mt1 : mt0;
            if (mt) { c_reg[k] = cn; h_reg[k] = hn; }
            hout[k] = mt ? hn : 0.f;
        }
        hdst[b0 * (NH / 2) + (hhbase >> 1)] = pack_bf16x2(h_reg[0], h_reg[1]);
        hdst[b1 * (NH / 2) + (hhbase >> 1)] = pack_bf16x2(h_reg[2], h_reg[3]);

        bar_arrive(grp, leaf);

        // hidden in the poll window: packed outp stores + next-step gx prefetch
        {
            int oc = (dir * NH + hhbase) >> 1;   // u32 col
            outp[(size_t)(b0 * NT + t_data) * NH + oc] = pack_bf16x2(hout[0], hout[1]);
            outp[(size_t)(b1 * NT + t_data) * NH + oc] = pack_bf16x2(hout[2], hout[3]);
        }
        if (t + 1 < NT) {
            int tn = dir ? (NT - 2 - t) : (t + 1);
            size_t base0 = (size_t)(b0 * NT + tn) * NG + hhbase;
            size_t base1 = (size_t)(b1 * NT + tn) * NG + hhbase;
#pragma unroll
            for (int g = 0; g < 4; g++) {
                float2 v0 = *(const float2*)&gxp[base0 + g * NH];
                float2 v1 = *(const float2*)&gxp[base1 + g * NH];
                gxv[g][0] = v0.x; gxv[g][1] = v0.y;
                gxv[g][2] = v1.x; gxv[g][3] = v1.y;
            }
        }

        bar_wait(grp, gen); gen++;
    }
}

// ---------------- emission FC (bf16 inputs) -------------------------------------
__global__ void emis_kernel(const float* __restrict__ fw, const float* __restrict__ fb)
{
    int gtid = blockIdx.x * blockDim.x + threadIdx.x;
    int w = gtid >> 5;
    int lane = threadIdx.x & 31;
    if (w >= MROWS) return;
    const unsigned* x = g_outbf1 + (size_t)w * NH;   // 512 u32 = 1024 bf16
    float acc[NC];
#pragma unroll
    for (int c = 0; c < NC; c++) acc[c] = 0.f;
    for (int k2 = lane; k2 < NH; k2 += 32) {
        unsigned p = x[k2];
        float lo = __uint_as_float(p << 16);
        float hi = __uint_as_float(p & 0xffff0000u);
        int k = 2 * k2;
#pragma unroll
        for (int c = 0; c < NC; c++)
            acc[c] += lo * fw[c * 2 * NH + k] + hi * fw[c * 2 * NH + k + 1];
    }
#pragma unroll
    for (int off = 16; off > 0; off >>= 1)
#pragma unroll
        for (int c = 0; c < NC; c++) acc[c] += __shfl_down_sync(0xffffffffu, acc[c], off);
    if (lane == 0) {
#pragma unroll
        for (int c = 0; c < NC; c++) g_emis[(size_t)w * NC + c] = acc[c] + fb[c];
    }
}

// ---------------- CRF -----------------------------------------------------------
__global__ void crf_kernel(const int* __restrict__ seq_len, const int* __restrict__ tags,
                           const float* __restrict__ trans, float* __restrict__ out)
{
    int b = blockIdx.x;
    int lane = threadIdx.x;
    __shared__ float tr[NC][NC + 1];
    __shared__ float vs[NC + 1], fs[NC + 1], vf[NC + 1], ff[NC + 1];

    for (int i = lane; i < NC * NC; i += 32) tr[i / NC][i % NC] = trans[i];
    if (lane < NC) { vs[lane] = 0.f; fs[lane] = NEGV; }
    __syncwarp();

    int sl = seq_len[b];
    for (int t = 0; t < NT; t++) {
        float vnew = 0.f, fnew = 0.f;
        if (lane < NC) {
            float emi = g_emis[(size_t)(b * NT + t) * NC + lane];
            float best = vs[0] + tr[0][lane]; int bi = 0;
            float m = fs[0] + tr[0][lane];
#pragma unroll
            for (int i = 1; i < NC; i++) {
                float v = vs[i] + tr[i][lane];
                if (v > best) { best = v; bi = i; }
                float fv = fs[i] + tr[i][lane];
                if (fv > m) m = fv;
            }
            float s = 0.f;
#pragma unroll
            for (int i = 0; i < NC; i++) s += expf(fs[i] + tr[i][lane] - m);
            vnew = best + emi;
            fnew = emi + m + logf(s);
            g_bt[(size_t)(b * NT + t) * NC + lane] = (unsigned char)bi;
        }
        __syncwarp();
        if (lane < NC && t < sl) { vs[lane] = vnew; fs[lane] = fnew; }
        __syncwarp();
    }
    if (lane < NC) {
        vf[lane] = vs[lane] + tr[lane][TSTOP];
        ff[lane] = fs[lane] + tr[lane][TSTOP];
    }
    __syncwarp();
    if (lane == 0) {
        int best = 0; float bv = vf[0];
        for (int j = 1; j < NC; j++) if (vf[j] > bv) { bv = vf[j]; best = j; }
        float m = ff[0];
        for (int j = 1; j < NC; j++) if (ff[j] > m) m = ff[j];
        float s = 0.f;
        for (int j = 0; j < NC; j++) s += expf(ff[j] - m);
        float fwd = m + logf(s);

        float gold = 0.f; int prev = TSTART;
        for (int t = 0; t < sl; t++) {
            int tg = tags[b * NT + t];
            gold += g_emis[(size_t)(b * NT + t) * NC + tg] + tr[prev][tg];
            prev = tg;
        }
        gold += tr[prev][TSTOP];
        g_lossb[b] = fwd - gold;

        int cur = best;
        for (int l = NT - 1; l >= 0; l--) {
            out[b * NT + l] = (l < sl) ? (float)cur : 0.f;
            if (l >= 1 && l <= sl - 1) cur = g_bt[(size_t)(b * NT + l) * NC + cur];
        }
    }
}

__global__ void loss_reduce(float* __restrict__ out)
{
    __shared__ float s[NB];
    int i = threadIdx.x;
    s[i] = g_lossb[i];
    __syncthreads();
    for (int off = NB / 2; off > 0; off >>= 1) {
        if (i < off) s[i] += s[i + off];
        __syncthreads();
    }
    if (i == 0) out[MROWS] = s[0] / (float)NB;
}

// ---------------- launcher ------------------------------------------------------
extern "C" void kernel_launch(void* const* d_in, const int* in_sizes, int n_in,
                              void* d_out, int out_size)
{
    const int*   tokens   = (const int*)d_in[0];
    const int*   seq_len  = (const int*)d_in[1];
    const int*   tags     = (const int*)d_in[3];
    const float* emb      = (const float*)d_in[4];
    const float* w_ih_l0  = (const float*)d_in[5];
    const float* w_hh_l0  = (const float*)d_in[6];
    const float* b_ih_l0  = (const float*)d_in[7];
    const float* b_hh_l0  = (const float*)d_in[8];
    const float* w_ih_l0r = (const float*)d_in[9];
    const float* w_hh_l0r = (const float*)d_in[10];
    const float* b_ih_l0r = (const float*)d_in[11];
    const float* b_hh_l0r = (const float*)d_in[12];
    const float* w_ih_l1  = (const float*)d_in[13];
    const float* w_hh_l1  = (const float*)d_in[14];
    const float* b_ih_l1  = (const float*)d_in[15];
    const float* b_hh_l1  = (const float*)d_in[16];
    const float* w_ih_l1r = (const float*)d_in[17];
    const float* w_hh_l1r = (const float*)d_in[18];
    const float* b_ih_l1r = (const float*)d_in[19];
    const float* b_hh_l1r = (const float*)d_in[20];
    const float* fc_w     = (const float*)d_in[21];
    const float* fc_b     = (const float*)d_in[22];
    const float* trans    = (const float*)d_in[23];
    float* out = (float*)d_out;

    static int smem_set = 0;
    if (!smem_set) {
        cudaFuncSetAttribute(lstm_persist_tc,
                             cudaFuncAttributeMaxDynamicSharedMemorySize, LSTM_SMEM);
        smem_set = 1;
    }

    unsigned* wbf0_0; cudaGetSymbolAddress((void**)&wbf0_0, g_wbf0);
    unsigned* wbf1_0; cudaGetSymbolAddress((void**)&wbf1_0, g_wbf1);
    unsigned* wbf0_1 = wbf0_0 + (size_t)NG * (NEP / 2);
    unsigned* wbf1_1 = wbf1_0 + (size_t)NG * NH;

    // ---- convert embedding table + input-projection weights to bf16 ----
    {
        size_t n_emb = (size_t)NV * (NEP / 2);
        conv_emb<<<(unsigned)((n_emb + 255) / 256), 256>>>(emb);
        size_t n_w0 = (size_t)NG * (NEP / 2);
        conv_w<<<(unsigned)((n_w0 + 255) / 256), 256>>>(w_ih_l0,  wbf0_0, NE, NEP / 2);
        conv_w<<<(unsigned)((n_w0 + 255) / 256), 256>>>(w_ih_l0r, wbf0_1, NE, NEP / 2);
        size_t n_w1 = (size_t)NG * NH;
        conv_w<<<(unsigned)((n_w1 + 255) / 256), 256>>>(w_ih_l1,  wbf1_0, 2 * NH, NH);
        conv_w<<<(unsigned)((n_w1 + 255) / 256), 256>>>(w_ih_l1r, wbf1_1, 2 * NH, NH);
    }

    reset_bar<<<1, 256>>>();

    dim3 ggx(NG / 128, MROWS / 128, 2);

    // ---- layer 0 ----
    gx_gemm_bf16<<<ggx, 256>>>(tokens,
                               wbf0_0, b_ih_l0, b_hh_l0,
                               wbf0_1, b_ih_l0r, b_hh_l0r, NEP / 2, 1);
    lstm_persist_tc<<<NBLK, 256, LSTM_SMEM>>>(seq_len, w_hh_l0, w_hh_l0r, 0);

    // ---- layer 1 ----
    gx_gemm_bf16<<<ggx, 256>>>(tokens,
                               wbf1_0, b_ih_l1, b_hh_l1,
                               wbf1_1, b_ih_l1r, b_hh_l1r, NH, 0);
    lstm_persist_tc<<<NBLK, 256, LSTM_SMEM>>>(seq_len, w_hh_l1, w_hh_l1r, 1);

    // ---- emissions + CRF ----
    emis_kernel<<<MROWS / 8, 256>>>(fc_w, fc_b);
    crf_kernel<<<NB, 32>>>(seq_len, tags, trans, out);
    loss_reduce<<<1, 128>>>(out);
}

// round 16
// speedup vs baseline: 2.3055x; 1.1236x over previous
#include <cuda_runtime.h>
#include <math.h>

#define NB 128
#define NT 256
#define NE 300
#define NEP 320     // padded embedding K (zero-fill)
#define NH 512
#define NG 2048     // 4*NH
#define NC 11
#define TSTART 9
#define TSTOP 10
#define NEGV -100000.0f
#define MROWS (NB*NT)   // 32768
#define NBLK 128        // persistent grid size
#define NV 50000

// ---------------- scratch (static device memory; no allocations) ----------------
__device__ float g_gxf[(size_t)MROWS * NG];       // forward-dir input projection (fp32)
__device__ float g_gxr[(size_t)MROWS * NG];       // reverse-dir input projection (fp32)
__device__ unsigned g_outbf0[(size_t)MROWS * (NH)];   // layer0 out, bf16x2
__device__ unsigned g_outbf1[(size_t)MROWS * (NH)];   // layer1 out, bf16x2
__device__ unsigned g_hbf[2 * 2 * NB * (NH / 2)]; // ping-pong h, packed bf16x2
__device__ unsigned g_embbf[(size_t)NV * (NEP / 2)];  // bf16x2 embedding table, padded
__device__ unsigned g_wbf0[2][(size_t)NG * (NEP / 2)];   // bf16x2 w_ih l0 / l0r
__device__ unsigned g_wbf1[2][(size_t)NG * (2 * NH / 2)];// bf16x2 w_ih l1 / l1r
__device__ float g_emis[(size_t)MROWS * NC];
__device__ unsigned char g_bt[(size_t)MROWS * NC];
__device__ float g_lossb[NB];

// ---------------- two-level tree barrier (R10-proven) ---------------------------
__device__ unsigned g_leafc[8 * 32];
__device__ unsigned g_rootc[2 * 32];
__device__ volatile unsigned g_genv[2 * 32];

__global__ void reset_bar()
{
    int i = threadIdx.x;
    if (i < 256) ((unsigned*)g_leafc)[i] = 0u;
    if (i < 64)  ((unsigned*)g_rootc)[i] = 0u;
    if (i < 64)  ((unsigned*)g_genv)[i]  = 0u;
}

__device__ __forceinline__ void bar_arrive(int grp, int leaf)
{
    __syncthreads();
    if (threadIdx.x == 0) {
        __threadfence();
        unsigned p = atomicAdd(&g_leafc[leaf * 32], 1u);
        if ((p & 15u) == 15u) {
            unsigned q = atomicAdd(&g_rootc[grp * 32], 1u);
            if ((q & 3u) == 3u) {
                __threadfence();
                g_genv[grp * 32] = (q >> 2) + 1u;
            }
        }
    }
}

__device__ __forceinline__ void bar_wait(int grp, unsigned my)
{
    if (threadIdx.x == 0) {
        while (g_genv[grp * 32] <= my) { }
    }
    __syncthreads();
}

// ---------------- numeric helpers -----------------------------------------------
__device__ __forceinline__ unsigned pack_bf16x2(float lo, float hi)
{
    unsigned r;
    asm("cvt.rn.bf16x2.f32 %0, %1, %2;" : "=r"(r) : "f"(hi), "f"(lo));
    return r;
}

__device__ __forceinline__ void mma_bf16(float* d, const unsigned* a, const unsigned* b)
{
    asm volatile(
        "mma.sync.aligned.m16n8k16.row.col.f32.bf16.bf16.f32 "
        "{%0,%1,%2,%3}, {%4,%5,%6,%7}, {%8,%9}, {%0,%1,%2,%3};\n"
        : "+f"(d[0]), "+f"(d[1]), "+f"(d[2]), "+f"(d[3])
        : "r"(a[0]), "r"(a[1]), "r"(a[2]), "r"(a[3]), "r"(b[0]), "r"(b[1]));
}

// ---------------- conversion kernels (run each replay; deterministic) -----------
__global__ void conv_emb(const float* __restrict__ emb)
{
    size_t i = (size_t)blockIdx.x * 256 + threadIdx.x;
    if (i >= (size_t)NV * (NEP / 2)) return;
    int c2  = (int)(i % (NEP / 2));
    size_t row = i / (NEP / 2);
    int c = 2 * c2;
    float lo = (c < NE)     ? emb[row * NE + c]     : 0.f;
    float hi = (c + 1 < NE) ? emb[row * NE + c + 1] : 0.f;
    g_embbf[i] = pack_bf16x2(lo, hi);
}

__global__ void conv_w(const float* __restrict__ W, unsigned* __restrict__ dst,
                       int K, int Kp2)
{
    size_t i = (size_t)blockIdx.x * 256 + threadIdx.x;
    if (i >= (size_t)NG * Kp2) return;
    int c2  = (int)(i % Kp2);
    size_t row = i / Kp2;
    int c = 2 * c2;
    float lo = (c < K)     ? W[row * K + c]     : 0.f;
    float hi = (c + 1 < K) ? W[row * K + c + 1] : 0.f;
    dst[i] = pack_bf16x2(lo, hi);
}

// ---------------- bf16 gx GEMM with cp.async double buffering (R15 proven) ------
#define GXS 20   // row stride in u32 (16 used = 32 bf16 k)
__global__ __launch_bounds__(256) void gx_gemm_bf16(
    const int* __restrict__ tokens,
    const unsigned* __restrict__ Wb0, const float* __restrict__ bi0, const float* __restrict__ bh0,
    const unsigned* __restrict__ Wb1, const float* __restrict__ bi1, const float* __restrict__ bh1,
    int Kp2, int gather)
{
    int dir = blockIdx.z;
    const unsigned* W = dir ? Wb1 : Wb0;
    const float* bi = dir ? bi1 : bi0;
    const float* bh = dir ? bh1 : bh0;
    float* out = dir ? g_gxr : g_gxf;

    __shared__ unsigned As[2][128 * GXS];
    __shared__ unsigned Bs[2][128 * GXS];

    int tid  = threadIdx.x;
    int warp = tid >> 5;
    int lane = tid & 31;
    int quad = lane >> 2;
    int l4   = lane & 3;
    int wm   = (warp >> 1) * 32;
    int wn   = (warp & 1) * 64;

    int m0 = blockIdx.y * 128;
    int n0 = blockIdx.x * 128;

    float acc[2][8][4];
#pragma unroll
    for (int i = 0; i < 2; i++)
#pragma unroll
        for (int j = 0; j < 8; j++)
#pragma unroll
            for (int q = 0; q < 4; q++) acc[i][j][q] = 0.f;

    int kiters = Kp2 >> 4;

    auto do_stage = [&](int buf, int kt) {
        int k2_0 = kt << 4;
#pragma unroll
        for (int r = 0; r < 2; r++) {
            int f  = tid + 256 * r;
            int mm = f >> 2;
            int sg = (f & 3) * 4;
            int row = m0 + mm;
            const unsigned* src = gather
                ? (g_embbf + (size_t)tokens[row] * (NEP / 2) + k2_0 + sg)
                : (g_outbf0 + (size_t)row * NH + k2_0 + sg);
            unsigned d = (unsigned)__cvta_generic_to_shared(&As[buf][mm * GXS + sg]);
            asm volatile("cp.async.cg.shared.global [%0], [%1], 16;" :: "r"(d), "l"(src));
        }
#pragma unroll
        for (int r = 0; r < 2; r++) {
            int f  = tid + 256 * r;
            int nn = f >> 2;
            int sg = (f & 3) * 4;
            const unsigned* src = W + (size_t)(n0 + nn) * Kp2 + k2_0 + sg;
            unsigned d = (unsigned)__cvta_generic_to_shared(&Bs[buf][nn * GXS + sg]);
            asm volatile("cp.async.cg.shared.global [%0], [%1], 16;" :: "r"(d), "l"(src));
        }
        asm volatile("cp.async.commit_group;");
    };

    do_stage(0, 0);

    for (int kt = 0; kt < kiters; kt++) {
        int buf = kt & 1;
        if (kt + 1 < kiters) {
            do_stage(buf ^ 1, kt + 1);
            asm volatile("cp.async.wait_group 1;");
        } else {
            asm volatile("cp.async.wait_group 0;");
        }
        __syncthreads();

        const unsigned* Ab = As[buf];
        const unsigned* Bb = Bs[buf];
#pragma unroll
        for (int kg = 0; kg < 16; kg += 8) {
            unsigned a[2][4], b[8][2];
#pragma unroll
            for (int mt = 0; mt < 2; mt++) {
                int mb = wm + mt * 16;
                a[mt][0] = Ab[(mb + quad) * GXS + kg + l4];
                a[mt][1] = Ab[(mb + quad + 8) * GXS + kg + l4];
                a[mt][2] = Ab[(mb + quad) * GXS + kg + l4 + 4];
                a[mt][3] = Ab[(mb + quad + 8) * GXS + kg + l4 + 4];
            }
#pragma unroll
            for (int nt = 0; nt < 8; nt++) {
                int nb = wn + nt * 8;
                b[nt][0] = Bb[(nb + quad) * GXS + kg + l4];
                b[nt][1] = Bb[(nb + quad) * GXS + kg + l4 + 4];
            }
#pragma unroll
            for (int mt = 0; mt < 2; mt++)
#pragma unroll
                for (int nt = 0; nt < 8; nt++)
                    mma_bf16(acc[mt][nt], a[mt], b[nt]);
        }
        __syncthreads();
    }

#pragma unroll
    for (int mt = 0; mt < 2; mt++) {
        int r0 = m0 + wm + mt * 16 + quad;
#pragma unroll
        for (int nt = 0; nt < 8; nt++) {
            int col = n0 + wn + nt * 8 + l4 * 2;
            float bsum0 = bi[col] + bh[col];
            float bsum1 = bi[col + 1] + bh[col + 1];
            float2 v0 = make_float2(acc[mt][nt][0] + bsum0, acc[mt][nt][1] + bsum1);
            float2 v1 = make_float2(acc[mt][nt][2] + bsum0, acc[mt][nt][3] + bsum1);
            *(float2*)&out[(size_t)r0 * NG + col] = v0;
            *(float2*)&out[(size_t)(r0 + 8) * NG + col] = v1;
        }
    }
}

// ---------------- bf16 persistent bidirectional LSTM, 8-deep h pipeline ---------
// All 8 h chunks staged at step start into 8 smem buffers (184KB total); chunk c
// consumed under wait_group 7-c. L2 latency paid once per step instead of 8x.
#define WSS2 40
#define HSS2 36
#define WS2_U (256 * WSS2)      // 10240 u32
#define HS2_U (NB * HSS2)       // 4608 u32 per chunk buffer
#define LSTM_SMEM ((WS2_U + 8 * HS2_U) * 4)   // 188416 bytes

__device__ __forceinline__ void stage_chunk(const unsigned* __restrict__ hsrc,
                                            unsigned* __restrict__ dstbase,
                                            int chunk, int tid)
{
#pragma unroll
    for (int r = 0; r < 4; r++) {
        int f   = tid + 256 * r;
        int row = f >> 3;
        int seg = f & 7;
        unsigned daddr = (unsigned)__cvta_generic_to_shared(dstbase + row * HSS2 + seg * 4);
        const unsigned* src = hsrc + row * (NH / 2) + chunk * 32 + seg * 4;
        asm volatile("cp.async.cg.shared.global [%0], [%1], 16;" :: "r"(daddr), "l"(src));
    }
}

__device__ __forceinline__ void wait_groups_leq(int n)
{
    switch (n) {
        case 0: asm volatile("cp.async.wait_group 0;"); break;
        case 1: asm volatile("cp.async.wait_group 1;"); break;
        case 2: asm volatile("cp.async.wait_group 2;"); break;
        case 3: asm volatile("cp.async.wait_group 3;"); break;
        case 4: asm volatile("cp.async.wait_group 4;"); break;
        case 5: asm volatile("cp.async.wait_group 5;"); break;
        case 6: asm volatile("cp.async.wait_group 6;"); break;
        default: asm volatile("cp.async.wait_group 7;"); break;
    }
}

__global__ __launch_bounds__(256) void lstm_persist_tc(
    const int* __restrict__ seq_len,
    const float* __restrict__ Whf, const float* __restrict__ Whr,
    int layer)
{
    extern __shared__ unsigned usmem[];
    unsigned* Wsm = usmem;
    unsigned* hsb = usmem + WS2_U;      // 8 chunk buffers, HS2_U apart

    int tid  = threadIdx.x;
    int bid  = blockIdx.x;
    int dir  = bid >> 6;
    int hc0  = (bid & 63) * 8;
    int grp  = dir;
    int leaf = bid >> 4;

    int w    = tid >> 5;
    int lane = tid & 31;
    int quad = lane >> 2;
    int l4   = lane & 3;

    const float* W   = dir ? Whr : Whf;
    const float* gxp = dir ? g_gxr : g_gxf;
    unsigned* outp = layer ? g_outbf1 : g_outbf0;

    unsigned gen = g_genv[grp * 32];

    for (int jj = tid; jj < 32 * 256; jj += 256) {
        int c = jj >> 8, k2 = jj & 255;
        int g = c >> 3, j = c & 7;
        const float* wr = W + (size_t)(g * NH + hc0 + j) * NH + 2 * k2;
        Wsm[k2 * WSS2 + c] = pack_bf16x2(wr[0], wr[1]);
    }

#pragma unroll
    for (int i = 0; i < 2; i++)
        g_hbf[bid * 512 + i * 256 + tid] = 0u;

    int b0 = 16 * w + quad;
    int b1 = b0 + 8;
    int hhbase = hc0 + 2 * l4;
    int sl0 = seq_len[b0];
    int sl1 = seq_len[b1];
    float c_reg[4] = {0.f, 0.f, 0.f, 0.f};
    float h_reg[4] = {0.f, 0.f, 0.f, 0.f};

    float gxv[4][4];
    {
        int t_data0 = dir ? (NT - 1) : 0;
        size_t base0 = (size_t)(b0 * NT + t_data0) * NG + hhbase;
        size_t base1 = (size_t)(b1 * NT + t_data0) * NG + hhbase;
#pragma unroll
        for (int g = 0; g < 4; g++) {
            float2 v0 = *(const float2*)&gxp[base0 + g * NH];
            float2 v1 = *(const float2*)&gxp[base1 + g * NH];
            gxv[g][0] = v0.x; gxv[g][1] = v0.y;
            gxv[g][2] = v1.x; gxv[g][3] = v1.y;
        }
    }

    bar_arrive(grp, leaf);
    bar_wait(grp, gen); gen++;

    for (int t = 0; t < NT; t++) {
        int rb = t & 1;
        int wbuf = 1 - rb;
        int t_data = dir ? (NT - 1 - t) : t;

        const unsigned* hsrc = g_hbf + rb * (2 * NB * (NH / 2)) + dir * (NB * (NH / 2));

        // stage ALL 8 chunks immediately after wake: one L2 latency for the step
#pragma unroll
        for (int c = 0; c < 8; c++) {
            stage_chunk(hsrc, hsb + c * HS2_U, c, tid);
            asm volatile("cp.async.commit_group;");
        }

        float acc[4][4];
#pragma unroll
        for (int g = 0; g < 4; g++)
#pragma unroll
            for (int q = 0; q < 4; q++) acc[g][q] = 0.f;

#pragma unroll
        for (int chunk = 0; chunk < 8; chunk++) {
            wait_groups_leq(7 - chunk);
            __syncthreads();

            const unsigned* cur = hsb + chunk * HS2_U;
            int k2g0 = chunk * 32;
#pragma unroll
            for (int s = 0; s < 4; s++) {
                int k2c = s * 8;
                unsigned a[4];
                a[0] = cur[b0 * HSS2 + k2c + l4];
                a[1] = cur[b1 * HSS2 + k2c + l4];
                a[2] = cur[b0 * HSS2 + k2c + l4 + 4];
                a[3] = cur[b1 * HSS2 + k2c + l4 + 4];
                int k2g = k2g0 + k2c;
#pragma unroll
                for (int g = 0; g < 4; g++) {
                    unsigned b[2];
                    b[0] = Wsm[(k2g + l4) * WSS2 + g * 8 + quad];
                    b[1] = Wsm[(k2g + l4 + 4) * WSS2 + g * 8 + quad];
                    mma_bf16(acc[g], a, b);
                }
            }
        }
        __syncthreads();   // all reads of hsb done before next step overwrites

        unsigned* hdst = g_hbf + wbuf * (2 * NB * (NH / 2)) + dir * (NB * (NH / 2));
        bool mt0 = t_data < sl0;
        bool mt1 = t_data < sl1;
        float hout[4];
#pragma unroll
        for (int k = 0; k < 4; k++) {
            int r  = k >> 1;
            float gi = acc[0][k] + gxv[0][k];
            float gf = acc[1][k] + gxv[1][k];
            float gg = acc[2][k] + gxv[2][k];
            float go = acc[3][k] + gxv[3][k];

            float iv = 1.f / (1.f + expf(-gi));
            float fv = 1.f / (1.f + expf(-gf));
            float ov = 1.f / (1.f + expf(-go));
            float gv = tanhf(gg);

            float cn = fv * c_reg[k] + iv * gv;
            float hn = ov * tanhf(cn);

            bool mt = r ? mt1 : mt0;
            if (mt) { c_reg[k] = cn; h_reg[k] = hn; }
            hout[k] = mt ? hn : 0.f;
        }
        hdst[b0 * (NH / 2) + (hhbase >> 1)] = pack_bf16x2(h_reg[0], h_reg[1]);
        hdst[b1 * (NH / 2) + (hhbase >> 1)] = pack_bf16x2(h_reg[2], h_reg[3]);

        bar_arrive(grp, leaf);

        // hidden in the poll window: packed outp stores + next-step gx prefetch
        {
            int oc = (dir * NH + hhbase) >> 1;
            outp[(size_t)(b0 * NT + t_data) * NH + oc] = pack_bf16x2(hout[0], hout[1]);
            outp[(size_t)(b1 * NT + t_data) * NH + oc] = pack_bf16x2(hout[2], hout[3]);
        }
        if (t + 1 < NT) {
            int tn = dir ? (NT - 2 - t) : (t + 1);
            size_t base0 = (size_t)(b0 * NT + tn) * NG + hhbase;
            size_t base1 = (size_t)(b1 * NT + tn) * NG + hhbase;
#pragma unroll
            for (int g = 0; g < 4; g++) {
                float2 v0 = *(const float2*)&gxp[base0 + g * NH];
                float2 v1 = *(const float2*)&gxp[base1 + g * NH];
                gxv[g][0] = v0.x; gxv[g][1] = v0.y;
                gxv[g][2] = v1.x; gxv[g][3] = v1.y;
            }
        }

        bar_wait(grp, gen); gen++;
    }
}

// ---------------- emission FC (bf16 inputs) -------------------------------------
__global__ void emis_kernel(const float* __restrict__ fw, const float* __restrict__ fb)
{
    int gtid = blockIdx.x * blockDim.x + threadIdx.x;
    int w = gtid >> 5;
    int lane = threadIdx.x & 31;
    if (w >= MROWS) return;
    const unsigned* x = g_outbf1 + (size_t)w * NH;
    float acc[NC];
#pragma unroll
    for (int c = 0; c < NC; c++) acc[c] = 0.f;
    for (int k2 = lane; k2 < NH; k2 += 32) {
        unsigned p = x[k2];
        float lo = __uint_as_float(p << 16);
        float hi = __uint_as_float(p & 0xffff0000u);
        int k = 2 * k2;
#pragma unroll
        for (int c = 0; c < NC; c++)
            acc[c] += lo * fw[c * 2 * NH + k] + hi * fw[c * 2 * NH + k + 1];
    }
#pragma unroll
    for (int off = 16; off > 0; off >>= 1)
#pragma unroll
        for (int c = 0; c < NC; c++) acc[c] += __shfl_down_sync(0xffffffffu, acc[c], off);
    if (lane == 0) {
#pragma unroll
        for (int c = 0; c < NC; c++) g_emis[(size_t)w * NC + c] = acc[c] + fb[c];
    }
}

// ---------------- CRF -----------------------------------------------------------
__global__ void crf_kernel(const int* __restrict__ seq_len, const int* __restrict__ tags,
                           const float* __restrict__ trans, float* __restrict__ out)
{
    int b = blockIdx.x;
    int lane = threadIdx.x;
    __shared__ float tr[NC][NC + 1];
    __shared__ float vs[NC + 1], fs[NC + 1], vf[NC + 1], ff[NC + 1];

    for (int i = lane; i < NC * NC; i += 32) tr[i / NC][i % NC] = trans[i];
    if (lane < NC) { vs[lane] = 0.f; fs[lane] = NEGV; }
    __syncwarp();

    int sl = seq_len[b];
    for (int t = 0; t < NT; t++) {
        float vnew = 0.f, fnew = 0.f;
        if (lane < NC) {
            float emi = g_emis[(size_t)(b * NT + t) * NC + lane];
            float best = vs[0] + tr[0][lane]; int bi = 0;
            float m = fs[0] + tr[0][lane];
#pragma unroll
            for (int i = 1; i < NC; i++) {
                float v = vs[i] + tr[i][lane];
                if (v > best) { best = v; bi = i; }
                float fv = fs[i] + tr[i][lane];
                if (fv > m) m = fv;
            }
            float s = 0.f;
#pragma unroll
            for (int i = 0; i < NC; i++) s += expf(fs[i] + tr[i][lane] - m);
            vnew = best + emi;
            fnew = emi + m + logf(s);
            g_bt[(size_t)(b * NT + t) * NC + lane] = (unsigned char)bi;
        }
        __syncwarp();
        if (lane < NC && t < sl) { vs[lane] = vnew; fs[lane] = fnew; }
        __syncwarp();
    }
    if (lane < NC) {
        vf[lane] = vs[lane] + tr[lane][TSTOP];
        ff[lane] = fs[lane] + tr[lane][TSTOP];
    }
    __syncwarp();
    if (lane == 0) {
        int best = 0; float bv = vf[0];
        for (int j = 1; j < NC; j++) if (vf[j] > bv) { bv = vf[j]; best = j; }
        float m = ff[0];
        for (int j = 1; j < NC; j++) if (ff[j] > m) m = ff[j];
        float s = 0.f;
        for (int j = 0; j < NC; j++) s += expf(ff[j] - m);
        float fwd = m + logf(s);

        float gold = 0.f; int prev = TSTART;
        for (int t = 0; t < sl; t++) {
            int tg = tags[b * NT + t];
            gold += g_emis[(size_t)(b * NT + t) * NC + tg] + tr[prev][tg];
            prev = tg;
        }
        gold += tr[prev][TSTOP];
        g_lossb[b] = fwd - gold;

        int cur = best;
        for (int l = NT - 1; l >= 0; l--) {
            out[b * NT + l] = (l < sl) ? (float)cur : 0.f;
            if (l >= 1 && l <= sl - 1) cur = g_bt[(size_t)(b * NT + l) * NC + cur];
        }
    }
}

__global__ void loss_reduce(float* __restrict__ out)
{
    __shared__ float s[NB];
    int i = threadIdx.x;
    s[i] = g_lossb[i];
    __syncthreads();
    for (int off = NB / 2; off > 0; off >>= 1) {
        if (i < off) s[i] += s[i + off];
        __syncthreads();
    }
    if (i == 0) out[MROWS] = s[0] / (float)NB;
}

// ---------------- launcher ------------------------------------------------------
extern "C" void kernel_launch(void* const* d_in, const int* in_sizes, int n_in,
                              void* d_out, int out_size)
{
    const int*   tokens   = (const int*)d_in[0];
    const int*   seq_len  = (const int*)d_in[1];
    const int*   tags     = (const int*)d_in[3];
    const float* emb      = (const float*)d_in[4];
    const float* w_ih_l0  = (const float*)d_in[5];
    const float* w_hh_l0  = (const float*)d_in[6];
    const float* b_ih_l0  = (const float*)d_in[7];
    const float* b_hh_l0  = (const float*)d_in[8];
    const float* w_ih_l0r = (const float*)d_in[9];
    const float* w_hh_l0r = (const float*)d_in[10];
    const float* b_ih_l0r = (const float*)d_in[11];
    const float* b_hh_l0r = (const float*)d_in[12];
    const float* w_ih_l1  = (const float*)d_in[13];
    const float* w_hh_l1  = (const float*)d_in[14];
    const float* b_ih_l1  = (const float*)d_in[15];
    const float* b_hh_l1  = (const float*)d_in[16];
    const float* w_ih_l1r = (const float*)d_in[17];
    const float* w_hh_l1r = (const float*)d_in[18];
    const float* b_ih_l1r = (const float*)d_in[19];
    const float* b_hh_l1r = (const float*)d_in[20];
    const float* fc_w     = (const float*)d_in[21];
    const float* fc_b     = (const float*)d_in[22];
    const float* trans    = (const float*)d_in[23];
    float* out = (float*)d_out;

    static int smem_set = 0;
    if (!smem_set) {
        cudaFuncSetAttribute(lstm_persist_tc,
                             cudaFuncAttributeMaxDynamicSharedMemorySize, LSTM_SMEM);
        smem_set = 1;
    }

    unsigned* wbf0_0; cudaGetSymbolAddress((void**)&wbf0_0, g_wbf0);
    unsigned* wbf1_0; cudaGetSymbolAddress((void**)&wbf1_0, g_wbf1);
    unsigned* wbf0_1 = wbf0_0 + (size_t)NG * (NEP / 2);
    unsigned* wbf1_1 = wbf1_0 + (size_t)NG * NH;

    // ---- convert embedding table + input-projection weights to bf16 ----
    {
        size_t n_emb = (size_t)NV * (NEP / 2);
        conv_emb<<<(unsigned)((n_emb + 255) / 256), 256>>>(emb);
        size_t n_w0 = (size_t)NG * (NEP / 2);
        conv_w<<<(unsigned)((n_w0 + 255) / 256), 256>>>(w_ih_l0,  wbf0_0, NE, NEP / 2);
        conv_w<<<(unsigned)((n_w0 + 255) / 256), 256>>>(w_ih_l0r, wbf0_1, NE, NEP / 2);
        size_t n_w1 = (size_t)NG * NH;
        conv_w<<<(unsigned)((n_w1 + 255) / 256), 256>>>(w_ih_l1,  wbf1_0, 2 * NH, NH);
        conv_w<<<(unsigned)((n_w1 + 255) / 256), 256>>>(w_ih_l1r, wbf1_1, 2 * NH, NH);
    }

    reset_bar<<<1, 256>>>();

    dim3 ggx(NG / 128, MROWS / 128, 2);

    // ---- layer 0 ----
    gx_gemm_bf16<<<ggx, 256>>>(tokens,
                               wbf0_0, b_ih_l0, b_hh_l0,
                               wbf0_1, b_ih_l0r, b_hh_l0r, NEP / 2, 1);
    lstm_persist_tc<<<NBLK, 256, LSTM_SMEM>>>(seq_len, w_hh_l0, w_hh_l0r, 0);

    // ---- layer 1 ----
    gx_gemm_bf16<<<ggx, 256>>>(tokens,
                               wbf1_0, b_ih_l1, b_hh_l1,
                               wbf1_1, b_ih_l1r, b_hh_l1r, NH, 0);
    lstm_persist_tc<<<NBLK, 256, LSTM_SMEM>>>(seq_len, w_hh_l1, w_hh_l1r, 1);

    // ---- emissions + CRF ----
    emis_kernel<<<MROWS / 8, 256>>>(fc_w, fc_b);
    crf_kernel<<<NB, 32>>>(seq_len, tags, trans, out);
    loss_reduce<<<1, 128>>>(out);
}